// round 9
// baseline (speedup 1.0000x reference)
#include <cuda_runtime.h>
#include <math.h>
#include <cstdint>

#define BSZ 16
#define SEQ 2048
#define DIM 1024
#define HD  128

// Scratch for Q, K, V projections — __device__ globals per the no-allocation rule.
__device__ float g_q[BSZ * SEQ * HD];
__device__ float g_k[BSZ * SEQ * HD];
__device__ float g_v[BSZ * SEQ * HD];

// ---------------------------------------------------------------------------
// Helpers
// ---------------------------------------------------------------------------
__device__ __forceinline__ uint32_t smem_u32(const void* p) {
    uint32_t a;
    asm("{ .reg .u64 t; cvta.to.shared.u64 t, %1; cvt.u32.u64 %0, t; }" : "=r"(a) : "l"(p));
    return a;
}

__device__ __forceinline__ void cp16(uint32_t dst, const void* src) {
    asm volatile("cp.async.cg.shared.global [%0], [%1], 16;" :: "r"(dst), "l"(src));
}
#define CP_COMMIT() asm volatile("cp.async.commit_group;" ::: "memory")
template <int N>
__device__ __forceinline__ void cp_wait() {
    asm volatile("cp.async.wait_group %0;" :: "n"(N) : "memory");
}

// RNA round to tf32 (unbiased; keeps value as fp32 with low 13 bits zero)
__device__ __forceinline__ uint32_t f2tf32(float x) {
    uint32_t r;
    asm("cvt.rna.tf32.f32 %0, %1;" : "=r"(r) : "f"(x));
    return r;
}
__device__ __forceinline__ float rna_tf32(float x) {
    return __uint_as_float(f2tf32(x));
}

// HMMA truncates b32 operands to tf32 (top 19 bits). lo = x - trunc(x), so
// passing (raw x, lo) as two operands reproduces x exactly.
__device__ __forceinline__ float tf32_lo(float x) {
    return x - __uint_as_float(__float_as_uint(x) & 0xFFFFE000u);
}

__device__ __forceinline__ void mma_tf32(float* c, const uint32_t* a, const uint32_t* b) {
    asm volatile(
        "mma.sync.aligned.m16n8k8.row.col.f32.tf32.tf32.f32 "
        "{%0,%1,%2,%3}, {%4,%5,%6,%7}, {%8,%9}, {%0,%1,%2,%3};"
        : "+f"(c[0]), "+f"(c[1]), "+f"(c[2]), "+f"(c[3])
        : "r"(a[0]), "r"(a[1]), "r"(a[2]), "r"(a[3]), "r"(b[0]), "r"(b[1]));
}

// ---------------------------------------------------------------------------
// Projection GEMM via mma.sync tf32, exact-A 2x:  (unchanged from R8 pass)
//   C = (A_raw + A_lo) . rna(B)
// ---------------------------------------------------------------------------
#define A_STRIDE 36
#define B_STRIDE 136
#define A_STAGE_B 18432
#define B_STAGE_B 17408
#define B_BASE_B  (2 * A_STAGE_B)
#define PROJ_SMEM (2 * A_STAGE_B + 2 * B_STAGE_B)
#define PROJ_NT   (DIM / 32)

__global__ __launch_bounds__(256, 2)
void proj_mma_kernel(const float* __restrict__ X,
                     const float* __restrict__ Wq,
                     const float* __restrict__ Wk,
                     const float* __restrict__ Wv)
{
    extern __shared__ float smf[];
    const uint32_t sbase = smem_u32(smf);
    const int tid  = threadIdx.x;
    const int wid  = tid >> 5;
    const int lane = tid & 31;
    const int g    = lane >> 2;
    const int tg   = lane & 3;
    const int wm   = wid >> 1;
    const int wn   = wid & 1;
    const int z    = blockIdx.y;
    const int m0   = blockIdx.x * 128;

    const float* __restrict__ W = (z == 0) ? Wq : ((z == 1) ? Wk : Wv);
    float* __restrict__ C       = (z == 0) ? g_q : ((z == 1) ? g_k : g_v);

    float acc[2][8][4];
#pragma unroll
    for (int mf = 0; mf < 2; mf++)
#pragma unroll
        for (int nf = 0; nf < 8; nf++)
#pragma unroll
            for (int r = 0; r < 4; r++) acc[mf][nf][r] = 0.f;

    auto stage = [&](int s, int t) {
        const int k0 = t * 32;
#pragma unroll
        for (int q = 0; q < 4; q++) {
            int c   = q * 256 + tid;
            int row = c >> 3;
            int ch  = c & 7;
            cp16(sbase + s * A_STAGE_B + row * (A_STRIDE * 4) + ch * 16,
                 &X[(size_t)(m0 + row) * DIM + k0 + ch * 4]);
        }
#pragma unroll
        for (int q = 0; q < 4; q++) {
            int c   = q * 256 + tid;
            int row = c >> 5;
            int ch  = c & 31;
            cp16(sbase + B_BASE_B + s * B_STAGE_B + row * (B_STRIDE * 4) + ch * 16,
                 &W[(size_t)(k0 + row) * HD + ch * 4]);
        }
        CP_COMMIT();
    };

    stage(0, 0);

    for (int t = 0; t < PROJ_NT; t++) {
        const int s = t & 1;
        if (t + 1 < PROJ_NT) {
            stage(s ^ 1, t + 1);
            cp_wait<1>();
        } else {
            cp_wait<0>();
        }
        __syncthreads();

        const float* As = smf + s * (A_STAGE_B / 4);
        const float* Bs = smf + (B_BASE_B / 4) + s * (B_STAGE_B / 4);

#pragma unroll
        for (int sub = 0; sub < 4; sub++) {
            const int k8 = sub * 8;
            uint32_t ah[2][4], al[2][4];
#pragma unroll
            for (int mf = 0; mf < 2; mf++) {
                const int r = wm * 32 + mf * 16 + g;
                float a0 = As[r * A_STRIDE + k8 + tg];
                float a1 = As[(r + 8) * A_STRIDE + k8 + tg];
                float a2 = As[r * A_STRIDE + k8 + tg + 4];
                float a3 = As[(r + 8) * A_STRIDE + k8 + tg + 4];
                ah[mf][0] = __float_as_uint(a0); al[mf][0] = __float_as_uint(tf32_lo(a0));
                ah[mf][1] = __float_as_uint(a1); al[mf][1] = __float_as_uint(tf32_lo(a1));
                ah[mf][2] = __float_as_uint(a2); al[mf][2] = __float_as_uint(tf32_lo(a2));
                ah[mf][3] = __float_as_uint(a3); al[mf][3] = __float_as_uint(tf32_lo(a3));
            }
#pragma unroll
            for (int nf = 0; nf < 8; nf++) {
                const int n = wn * 64 + nf * 8 + g;
                uint32_t bh[2] = {f2tf32(Bs[(k8 + tg) * B_STRIDE + n]),
                                  f2tf32(Bs[(k8 + tg + 4) * B_STRIDE + n])};
#pragma unroll
                for (int mf = 0; mf < 2; mf++) {
                    mma_tf32(acc[mf][nf], ah[mf], bh);
                    mma_tf32(acc[mf][nf], al[mf], bh);
                }
            }
        }
        __syncthreads();
    }

#pragma unroll
    for (int mf = 0; mf < 2; mf++) {
        const int row = m0 + wm * 32 + mf * 16 + g;
#pragma unroll
        for (int nf = 0; nf < 8; nf++) {
            const int col = wn * 64 + nf * 8 + tg * 2;
            *(float2*)&C[(size_t)row * HD + col]       = make_float2(acc[mf][nf][0], acc[mf][nf][1]);
            *(float2*)&C[(size_t)(row + 8) * HD + col] = make_float2(acc[mf][nf][2], acc[mf][nf][3]);
        }
    }
}

// ---------------------------------------------------------------------------
// Flash attention (causal), mma.sync tf32, cp.async-pipelined K/V.
// 512 threads, warps as 8M x 2N.
// QK^T: Q RNA-rounded once at CTA load; K exact (raw + in-loop lo).   2 MMAs.
// PV:   P RNA-rounded once; V exact (raw + in-loop lo).               2 MMAs.
// K double-buffered (prefetch j+1 during tile j); V single-buffered,
// issued at tile top, awaited only before PV (hides under QK+softmax).
// Smem floats: Qs[128][132] Kb[2][64][132] Vh[64][136] Ps[128][68] Red
// ---------------------------------------------------------------------------
#define ATT_BQ 128
#define ATT_BK 64
#define QSTR 132
#define KSTR 132
#define VSTR 136
#define PSTR 68
#define QS_OFF 0
#define KB_OFF (ATT_BQ * QSTR)                     // 16896
#define KB_SZ  (ATT_BK * KSTR)                     // 8448
#define VH_OFF (KB_OFF + 2 * KB_SZ)                // 33792
#define PS_OFF (VH_OFF + ATT_BK * VSTR)            // 42496
#define RED_OFF (PS_OFF + ATT_BQ * PSTR)           // 51200
#define ATT_SMEM ((RED_OFF + ATT_BQ * 2 * 2) * 4)  // 206848 B

__global__ __launch_bounds__(512, 1)
void attn_mma_kernel(float* __restrict__ out)
{
    extern __shared__ float sm[];
    float* Qs  = sm + QS_OFF;
    float* Vh  = sm + VH_OFF;
    float* Ps  = sm + PS_OFF;
    float2* Red = (float2*)(sm + RED_OFF);
    const uint32_t sbase = smem_u32(sm);

    const int qt   = gridDim.x - 1 - blockIdx.x;   // heavy tiles first
    const int b    = blockIdx.y;
    const int tid  = threadIdx.x;
    const int lane = tid & 31;
    const int wid  = tid >> 5;
    const int g    = lane >> 2;
    const int tg   = lane & 3;
    const int wm   = wid >> 1;        // 0..7
    const int wn   = wid & 1;         // 0..1
    const int r0   = wm * 16 + g;     // warp row 0 (tile-local)
    const float scale = 0.08838834764831845f;      // 1/sqrt(128)

    const int ntiles = 2 * qt + 2;
    const float* __restrict__ Kbase = g_k + (size_t)b * SEQ * HD;
    const float* __restrict__ Vbase = g_v + (size_t)b * SEQ * HD;

    // per-thread cp.async slice coordinates for a 64x128 tile
    const int ld_row = tid >> 3;            // 0..63
    const int ld_c4  = (tid & 7) * 16;      // 0,16,..112 (columns, 4 float4s/thread)

    // ---- prefetch K(0) ----
#pragma unroll
    for (int u = 0; u < 4; u++)
        cp16(sbase + (KB_OFF + ld_row * KSTR + ld_c4 + u * 4) * 4,
             &Kbase[(size_t)ld_row * HD + ld_c4 + u * 4]);
    CP_COMMIT();

    // ---- load Q tile (scaled, RNA-rounded to tf32 once) ----
    const float* __restrict__ Qg = g_q + ((size_t)b * SEQ + (size_t)qt * ATT_BQ) * HD;
#pragma unroll
    for (int t = 0; t < 8; t++) {
        int idx = t * 512 + tid;      // float4 idx over 128x128
        int row = idx >> 5;
        int c4  = (idx & 31) * 4;
        float4 v = *(const float4*)&Qg[(size_t)row * HD + c4];
        v.x = rna_tf32(v.x * scale); v.y = rna_tf32(v.y * scale);
        v.z = rna_tf32(v.z * scale); v.w = rna_tf32(v.w * scale);
        *(float4*)&Qs[row * QSTR + c4] = v;
    }

    float m_i[2] = {-1e30f, -1e30f};
    float l_i[2] = {0.f, 0.f};
    float o[8][4];
#pragma unroll
    for (int nf = 0; nf < 8; nf++)
#pragma unroll
        for (int r = 0; r < 4; r++) o[nf][r] = 0.f;

    const int rowg = qt * ATT_BQ + r0;

    for (int j = 0; j < ntiles; j++) {
        const float* Ks = sm + KB_OFF + (j & 1) * KB_SZ;

        // all warps done with PV(j-1) (Vh, Ps) and QK(j-1) (other K buffer)
        __syncthreads();

        // issue V(j) into Vh
#pragma unroll
        for (int u = 0; u < 4; u++)
            cp16(sbase + (VH_OFF + ld_row * VSTR + ld_c4 + u * 4) * 4,
                 &Vbase[((size_t)j * ATT_BK + ld_row) * HD + ld_c4 + u * 4]);
        CP_COMMIT();
        // issue K(j+1) into the other buffer (clamped to stay in bounds)
        {
            const int jn = (j + 1 < ntiles) ? (j + 1) : j;
#pragma unroll
            for (int u = 0; u < 4; u++)
                cp16(sbase + (KB_OFF + ((j + 1) & 1) * KB_SZ + ld_row * KSTR + ld_c4 + u * 4) * 4,
                     &Kbase[((size_t)jn * ATT_BK + ld_row) * HD + ld_c4 + u * 4]);
            CP_COMMIT();
        }

        cp_wait<2>();      // K(j) arrived (V(j), K(j+1) still in flight)
        __syncthreads();

        // ---- S = Q . K^T  (warp: 16 rows x 32 cols), exact-K 2x ----
        float s[4][4];
#pragma unroll
        for (int nf = 0; nf < 4; nf++)
#pragma unroll
            for (int r = 0; r < 4; r++) s[nf][r] = 0.f;

#pragma unroll
        for (int k8 = 0; k8 < 16; k8++) {
            const int k = k8 * 8;
            uint32_t ah[4] = {__float_as_uint(Qs[r0 * QSTR + k + tg]),
                              __float_as_uint(Qs[(r0 + 8) * QSTR + k + tg]),
                              __float_as_uint(Qs[r0 * QSTR + k + tg + 4]),
                              __float_as_uint(Qs[(r0 + 8) * QSTR + k + tg + 4])};
#pragma unroll
            for (int nf = 0; nf < 4; nf++) {
                const int kr = (wn * 32 + nf * 8 + g) * KSTR + k;
                float b0 = Ks[kr + tg];
                float b1 = Ks[kr + tg + 4];
                uint32_t bh[2] = {__float_as_uint(b0), __float_as_uint(b1)};
                uint32_t bl[2] = {__float_as_uint(tf32_lo(b0)), __float_as_uint(tf32_lo(b1))};
                mma_tf32(s[nf], ah, bh);
                mma_tf32(s[nf], ah, bl);
            }
        }

        // ---- causal mask (only last two kv tiles can intersect the diagonal) ----
        if (j >= 2 * qt) {
            const int colbase = j * ATT_BK + wn * 32;
#pragma unroll
            for (int nf = 0; nf < 4; nf++) {
                int c0 = colbase + nf * 8 + tg * 2;
                if (c0 > rowg)          s[nf][0] = -1e30f;
                if (c0 + 1 > rowg)      s[nf][1] = -1e30f;
                if (c0 > rowg + 8)      s[nf][2] = -1e30f;
                if (c0 + 1 > rowg + 8)  s[nf][3] = -1e30f;
            }
        }

        // ---- local (32-col) row max ----
        float mx0 = -1e30f, mx1 = -1e30f;
#pragma unroll
        for (int nf = 0; nf < 4; nf++) {
            mx0 = fmaxf(mx0, fmaxf(s[nf][0], s[nf][1]));
            mx1 = fmaxf(mx1, fmaxf(s[nf][2], s[nf][3]));
        }
        mx0 = fmaxf(mx0, __shfl_xor_sync(0xffffffffu, mx0, 1));
        mx0 = fmaxf(mx0, __shfl_xor_sync(0xffffffffu, mx0, 2));
        mx1 = fmaxf(mx1, __shfl_xor_sync(0xffffffffu, mx1, 1));
        mx1 = fmaxf(mx1, __shfl_xor_sync(0xffffffffu, mx1, 2));

        // ---- exp relative to local max + local sums ----
        float rs0 = 0.f, rs1 = 0.f;
#pragma unroll
        for (int nf = 0; nf < 4; nf++) {
            s[nf][0] = __expf(s[nf][0] - mx0);
            s[nf][1] = __expf(s[nf][1] - mx0);
            s[nf][2] = __expf(s[nf][2] - mx1);
            s[nf][3] = __expf(s[nf][3] - mx1);
            rs0 += s[nf][0] + s[nf][1];
            rs1 += s[nf][2] + s[nf][3];
        }
        rs0 += __shfl_xor_sync(0xffffffffu, rs0, 1);
        rs0 += __shfl_xor_sync(0xffffffffu, rs0, 2);
        rs1 += __shfl_xor_sync(0xffffffffu, rs1, 1);
        rs1 += __shfl_xor_sync(0xffffffffu, rs1, 2);

        // ---- pairwise merge with the other N-warp ----
        if (tg == 0) {
            Red[r0 * 2 + wn]       = make_float2(mx0, rs0);
            Red[(r0 + 8) * 2 + wn] = make_float2(mx1, rs1);
        }
        asm volatile("bar.sync %0, 64;" :: "r"(1 + wm) : "memory");
        float2 p0 = Red[r0 * 2 + (wn ^ 1)];
        float2 p1 = Red[(r0 + 8) * 2 + (wn ^ 1)];

        float mn0 = fmaxf(m_i[0], fmaxf(mx0, p0.x));
        float mn1 = fmaxf(m_i[1], fmaxf(mx1, p1.x));
        float f0  = __expf(mx0 - mn0);
        float f1  = __expf(mx1 - mn1);
        float al0 = __expf(m_i[0] - mn0);
        float al1 = __expf(m_i[1] - mn1);
        l_i[0] = l_i[0] * al0 + rs0 * f0 + p0.y * __expf(p0.x - mn0);
        l_i[1] = l_i[1] * al1 + rs1 * f1 + p1.y * __expf(p1.x - mn1);
        m_i[0] = mn0;
        m_i[1] = mn1;

#pragma unroll
        for (int nf = 0; nf < 8; nf++) {
            o[nf][0] *= al0; o[nf][1] *= al0;
            o[nf][2] *= al1; o[nf][3] *= al1;
        }

        // ---- stage P (rescaled to global max, RNA-rounded to tf32) ----
#pragma unroll
        for (int nf = 0; nf < 4; nf++) {
            float2 w0 = make_float2(rna_tf32(s[nf][0] * f0), rna_tf32(s[nf][1] * f0));
            float2 w1 = make_float2(rna_tf32(s[nf][2] * f1), rna_tf32(s[nf][3] * f1));
            *(float2*)&Ps[r0 * PSTR + wn * 32 + nf * 8 + tg * 2]       = w0;
            *(float2*)&Ps[(r0 + 8) * PSTR + wn * 32 + nf * 8 + tg * 2] = w1;
        }

        cp_wait<1>();      // V(j) arrived (K(j+1) still in flight)
        __syncthreads();   // V + P visible to all warps

        // ---- O += P . V  (warp: 16 rows x 64 out-cols), exact-V 2x ----
#pragma unroll
        for (int k8 = 0; k8 < 8; k8++) {
            const int k = k8 * 8;
            uint32_t ph[4] = {
                __float_as_uint(Ps[r0 * PSTR + k + tg]),
                __float_as_uint(Ps[(r0 + 8) * PSTR + k + tg]),
                __float_as_uint(Ps[r0 * PSTR + k + tg + 4]),
                __float_as_uint(Ps[(r0 + 8) * PSTR + k + tg + 4])};
#pragma unroll
            for (int nf = 0; nf < 8; nf++) {
                const int col = wn * 64 + nf * 8 + g;
                float v0 = Vh[(k + tg) * VSTR + col];
                float v1 = Vh[(k + tg + 4) * VSTR + col];
                uint32_t vh[2] = {__float_as_uint(v0), __float_as_uint(v1)};
                uint32_t vl[2] = {__float_as_uint(tf32_lo(v0)), __float_as_uint(tf32_lo(v1))};
                mma_tf32(o[nf], ph, vh);
                mma_tf32(o[nf], ph, vl);
            }
        }
    }

    // ---- normalize and store ----
    const float inv0 = 1.f / l_i[0];
    const float inv1 = 1.f / l_i[1];
    const size_t orow = (size_t)b * SEQ + (size_t)qt * ATT_BQ + r0;
#pragma unroll
    for (int nf = 0; nf < 8; nf++) {
        const int col = wn * 64 + nf * 8 + tg * 2;
        *(float2*)&out[orow * HD + col]       = make_float2(o[nf][0] * inv0, o[nf][1] * inv0);
        *(float2*)&out[(orow + 8) * HD + col] = make_float2(o[nf][2] * inv1, o[nf][3] * inv1);
    }
}

// ---------------------------------------------------------------------------
extern "C" void kernel_launch(void* const* d_in, const int* in_sizes, int n_in,
                              void* d_out, int out_size)
{
    const float* x  = (const float*)d_in[0];
    const float* wq = (const float*)d_in[1];
    const float* wk = (const float*)d_in[2];
    const float* wv = (const float*)d_in[3];
    float* out = (float*)d_out;

    cudaFuncSetAttribute(proj_mma_kernel,
                         cudaFuncAttributeMaxDynamicSharedMemorySize, PROJ_SMEM);
    cudaFuncSetAttribute(attn_mma_kernel,
                         cudaFuncAttributeMaxDynamicSharedMemorySize, ATT_SMEM);

    dim3 gridP((BSZ * SEQ) / 128, 3);
    proj_mma_kernel<<<gridP, 256, PROJ_SMEM>>>(x, wq, wk, wv);

    dim3 gridA(SEQ / ATT_BQ, BSZ);
    attn_mma_kernel<<<gridA, 512, ATT_SMEM>>>(out);
}

// round 10
// speedup vs baseline: 1.2670x; 1.2670x over previous
#include <cuda_runtime.h>
#include <math.h>
#include <cstdint>

#define BSZ 16
#define SEQ 2048
#define DIM 1024
#define HD  128

// Scratch for Q, K, V projections — __device__ globals per the no-allocation rule.
__device__ float g_q[BSZ * SEQ * HD];
__device__ float g_k[BSZ * SEQ * HD];
__device__ float g_v[BSZ * SEQ * HD];

// ---------------------------------------------------------------------------
// Helpers
// ---------------------------------------------------------------------------
__device__ __forceinline__ uint32_t smem_u32(const void* p) {
    uint32_t a;
    asm("{ .reg .u64 t; cvta.to.shared.u64 t, %1; cvt.u32.u64 %0, t; }" : "=r"(a) : "l"(p));
    return a;
}

__device__ __forceinline__ void cp16(uint32_t dst, const void* src) {
    asm volatile("cp.async.cg.shared.global [%0], [%1], 16;" :: "r"(dst), "l"(src));
}
#define CP_COMMIT() asm volatile("cp.async.commit_group;" ::: "memory")
template <int N>
__device__ __forceinline__ void cp_wait() {
    asm volatile("cp.async.wait_group %0;" :: "n"(N) : "memory");
}

// RNA round to tf32 (unbiased; keeps value as fp32 with low 13 bits zero)
__device__ __forceinline__ uint32_t f2tf32(float x) {
    uint32_t r;
    asm("cvt.rna.tf32.f32 %0, %1;" : "=r"(r) : "f"(x));
    return r;
}
__device__ __forceinline__ float rna_tf32(float x) {
    return __uint_as_float(f2tf32(x));
}

// HMMA truncates b32 operands to tf32 (top 19 bits). lo = x - trunc(x).
__device__ __forceinline__ float tf32_lo(float x) {
    return x - __uint_as_float(__float_as_uint(x) & 0xFFFFE000u);
}

__device__ __forceinline__ void mma_tf32(float* c, const uint32_t* a, const uint32_t* b) {
    asm volatile(
        "mma.sync.aligned.m16n8k8.row.col.f32.tf32.tf32.f32 "
        "{%0,%1,%2,%3}, {%4,%5,%6,%7}, {%8,%9}, {%0,%1,%2,%3};"
        : "+f"(c[0]), "+f"(c[1]), "+f"(c[2]), "+f"(c[3])
        : "r"(a[0]), "r"(a[1]), "r"(a[2]), "r"(a[3]), "r"(b[0]), "r"(b[1]));
}

// ---------------------------------------------------------------------------
// Projection GEMM via mma.sync tf32, exact-A 2x:  (unchanged from R8 pass)
//   C = (A_raw + A_lo) . rna(B)
// ---------------------------------------------------------------------------
#define A_STRIDE 36
#define B_STRIDE 136
#define A_STAGE_B 18432
#define B_STAGE_B 17408
#define B_BASE_B  (2 * A_STAGE_B)
#define PROJ_SMEM (2 * A_STAGE_B + 2 * B_STAGE_B)
#define PROJ_NT   (DIM / 32)

__global__ __launch_bounds__(256, 2)
void proj_mma_kernel(const float* __restrict__ X,
                     const float* __restrict__ Wq,
                     const float* __restrict__ Wk,
                     const float* __restrict__ Wv)
{
    extern __shared__ float smf[];
    const uint32_t sbase = smem_u32(smf);
    const int tid  = threadIdx.x;
    const int wid  = tid >> 5;
    const int lane = tid & 31;
    const int g    = lane >> 2;
    const int tg   = lane & 3;
    const int wm   = wid >> 1;
    const int wn   = wid & 1;
    const int z    = blockIdx.y;
    const int m0   = blockIdx.x * 128;

    const float* __restrict__ W = (z == 0) ? Wq : ((z == 1) ? Wk : Wv);
    float* __restrict__ C       = (z == 0) ? g_q : ((z == 1) ? g_k : g_v);

    float acc[2][8][4];
#pragma unroll
    for (int mf = 0; mf < 2; mf++)
#pragma unroll
        for (int nf = 0; nf < 8; nf++)
#pragma unroll
            for (int r = 0; r < 4; r++) acc[mf][nf][r] = 0.f;

    auto stage = [&](int s, int t) {
        const int k0 = t * 32;
#pragma unroll
        for (int q = 0; q < 4; q++) {
            int c   = q * 256 + tid;
            int row = c >> 3;
            int ch  = c & 7;
            cp16(sbase + s * A_STAGE_B + row * (A_STRIDE * 4) + ch * 16,
                 &X[(size_t)(m0 + row) * DIM + k0 + ch * 4]);
        }
#pragma unroll
        for (int q = 0; q < 4; q++) {
            int c   = q * 256 + tid;
            int row = c >> 5;
            int ch  = c & 31;
            cp16(sbase + B_BASE_B + s * B_STAGE_B + row * (B_STRIDE * 4) + ch * 16,
                 &W[(size_t)(k0 + row) * HD + ch * 4]);
        }
        CP_COMMIT();
    };

    stage(0, 0);

    for (int t = 0; t < PROJ_NT; t++) {
        const int s = t & 1;
        if (t + 1 < PROJ_NT) {
            stage(s ^ 1, t + 1);
            cp_wait<1>();
        } else {
            cp_wait<0>();
        }
        __syncthreads();

        const float* As = smf + s * (A_STAGE_B / 4);
        const float* Bs = smf + (B_BASE_B / 4) + s * (B_STAGE_B / 4);

#pragma unroll
        for (int sub = 0; sub < 4; sub++) {
            const int k8 = sub * 8;
            uint32_t ah[2][4], al[2][4];
#pragma unroll
            for (int mf = 0; mf < 2; mf++) {
                const int r = wm * 32 + mf * 16 + g;
                float a0 = As[r * A_STRIDE + k8 + tg];
                float a1 = As[(r + 8) * A_STRIDE + k8 + tg];
                float a2 = As[r * A_STRIDE + k8 + tg + 4];
                float a3 = As[(r + 8) * A_STRIDE + k8 + tg + 4];
                ah[mf][0] = __float_as_uint(a0); al[mf][0] = __float_as_uint(tf32_lo(a0));
                ah[mf][1] = __float_as_uint(a1); al[mf][1] = __float_as_uint(tf32_lo(a1));
                ah[mf][2] = __float_as_uint(a2); al[mf][2] = __float_as_uint(tf32_lo(a2));
                ah[mf][3] = __float_as_uint(a3); al[mf][3] = __float_as_uint(tf32_lo(a3));
            }
#pragma unroll
            for (int nf = 0; nf < 8; nf++) {
                const int n = wn * 64 + nf * 8 + g;
                uint32_t bh[2] = {f2tf32(Bs[(k8 + tg) * B_STRIDE + n]),
                                  f2tf32(Bs[(k8 + tg + 4) * B_STRIDE + n])};
#pragma unroll
                for (int mf = 0; mf < 2; mf++) {
                    mma_tf32(acc[mf][nf], ah[mf], bh);
                    mma_tf32(acc[mf][nf], al[mf], bh);
                }
            }
        }
        __syncthreads();
    }

#pragma unroll
    for (int mf = 0; mf < 2; mf++) {
        const int row = m0 + wm * 32 + mf * 16 + g;
#pragma unroll
        for (int nf = 0; nf < 8; nf++) {
            const int col = wn * 64 + nf * 8 + tg * 2;
            *(float2*)&C[(size_t)row * HD + col]       = make_float2(acc[mf][nf][0], acc[mf][nf][1]);
            *(float2*)&C[(size_t)(row + 8) * HD + col] = make_float2(acc[mf][nf][2], acc[mf][nf][3]);
        }
    }
}

// ---------------------------------------------------------------------------
// Flash attention (causal), mma.sync tf32 — R8 structure, single-MMA paths.
// 512 threads, warps as 8M x 2N.
// ALL operands (Q, K, P, V) RNA-rounded once at their smem write (unbiased),
// so every MMA is a single instruction and inner loops are pure LDS -> MMA.
// Smem floats: Qs[128][132] Ks[64][132] Vh[64][136] Ps[128][68] Red
// ---------------------------------------------------------------------------
#define ATT_BQ 128
#define ATT_BK 64
#define QSTR 132
#define KSTR 132
#define VSTR 136
#define PSTR 68
#define QS_OFF 0
#define KS_OFF (ATT_BQ * QSTR)                     // 16896
#define VH_OFF (KS_OFF + ATT_BK * KSTR)            // 25344
#define PS_OFF (VH_OFF + ATT_BK * VSTR)            // 34048
#define RED_OFF (PS_OFF + ATT_BQ * PSTR)           // 42752
#define ATT_SMEM ((RED_OFF + ATT_BQ * 2 * 2) * 4)  // 173056 B

__global__ __launch_bounds__(512, 1)
void attn_mma_kernel(float* __restrict__ out)
{
    extern __shared__ float sm[];
    float* Qs  = sm + QS_OFF;
    float* Ks  = sm + KS_OFF;
    float* Vh  = sm + VH_OFF;
    float* Ps  = sm + PS_OFF;
    float2* Red = (float2*)(sm + RED_OFF);

    const int qt   = gridDim.x - 1 - blockIdx.x;   // heavy tiles first
    const int b    = blockIdx.y;
    const int tid  = threadIdx.x;
    const int lane = tid & 31;
    const int wid  = tid >> 5;
    const int g    = lane >> 2;
    const int tg   = lane & 3;
    const int wm   = wid >> 1;        // 0..7
    const int wn   = wid & 1;         // 0..1
    const int r0   = wm * 16 + g;     // warp row 0 (tile-local)
    const float scale = 0.08838834764831845f;      // 1/sqrt(128)

    // ---- load Q tile (scaled, RNA-rounded once) ----
    const float* __restrict__ Qg = g_q + ((size_t)b * SEQ + (size_t)qt * ATT_BQ) * HD;
#pragma unroll
    for (int t = 0; t < 8; t++) {
        int idx = t * 512 + tid;      // float4 idx over 128x128
        int row = idx >> 5;
        int c4  = (idx & 31) * 4;
        float4 v = *(const float4*)&Qg[(size_t)row * HD + c4];
        v.x = rna_tf32(v.x * scale); v.y = rna_tf32(v.y * scale);
        v.z = rna_tf32(v.z * scale); v.w = rna_tf32(v.w * scale);
        *(float4*)&Qs[row * QSTR + c4] = v;
    }

    float m_i[2] = {-1e30f, -1e30f};
    float l_i[2] = {0.f, 0.f};
    float o[8][4];
#pragma unroll
    for (int nf = 0; nf < 8; nf++)
#pragma unroll
        for (int r = 0; r < 4; r++) o[nf][r] = 0.f;

    const int ntiles = 2 * qt + 2;
    const int rowg   = qt * ATT_BQ + r0;

    for (int j = 0; j < ntiles; j++) {
        const float* __restrict__ Kg = g_k + ((size_t)b * SEQ + (size_t)j * ATT_BK) * HD;
        const float* __restrict__ Vg = g_v + ((size_t)b * SEQ + (size_t)j * ATT_BK) * HD;

        __syncthreads();   // all warps done reading previous Ks/Vh/Ps

        // K and V: RNA-round once at fill (MMA truncation is then a no-op)
#pragma unroll
        for (int t = 0; t < 4; t++) {
            int idx = t * 512 + tid;  // float4 idx over 64x128
            int row = idx >> 5;
            int c4  = (idx & 31) * 4;
            float4 kv = *(const float4*)&Kg[(size_t)row * HD + c4];
            kv.x = rna_tf32(kv.x); kv.y = rna_tf32(kv.y);
            kv.z = rna_tf32(kv.z); kv.w = rna_tf32(kv.w);
            *(float4*)&Ks[row * KSTR + c4] = kv;
            float4 v = *(const float4*)&Vg[(size_t)row * HD + c4];
            v.x = rna_tf32(v.x); v.y = rna_tf32(v.y);
            v.z = rna_tf32(v.z); v.w = rna_tf32(v.w);
            *(float4*)&Vh[row * VSTR + c4] = v;
        }
        __syncthreads();

        // ---- S = Q . K^T  (warp: 16 rows x 32 cols), single MMA ----
        float s[4][4];
#pragma unroll
        for (int nf = 0; nf < 4; nf++)
#pragma unroll
            for (int r = 0; r < 4; r++) s[nf][r] = 0.f;

#pragma unroll
        for (int k8 = 0; k8 < 16; k8++) {
            const int k = k8 * 8;
            uint32_t ah[4] = {__float_as_uint(Qs[r0 * QSTR + k + tg]),
                              __float_as_uint(Qs[(r0 + 8) * QSTR + k + tg]),
                              __float_as_uint(Qs[r0 * QSTR + k + tg + 4]),
                              __float_as_uint(Qs[(r0 + 8) * QSTR + k + tg + 4])};
#pragma unroll
            for (int nf = 0; nf < 4; nf++) {
                const int kr = (wn * 32 + nf * 8 + g) * KSTR + k;
                uint32_t bh[2] = {__float_as_uint(Ks[kr + tg]),
                                  __float_as_uint(Ks[kr + tg + 4])};
                mma_tf32(s[nf], ah, bh);
            }
        }

        // ---- causal mask (only last two kv tiles can intersect the diagonal) ----
        if (j >= 2 * qt) {
            const int colbase = j * ATT_BK + wn * 32;
#pragma unroll
            for (int nf = 0; nf < 4; nf++) {
                int c0 = colbase + nf * 8 + tg * 2;
                if (c0 > rowg)          s[nf][0] = -1e30f;
                if (c0 + 1 > rowg)      s[nf][1] = -1e30f;
                if (c0 > rowg + 8)      s[nf][2] = -1e30f;
                if (c0 + 1 > rowg + 8)  s[nf][3] = -1e30f;
            }
        }

        // ---- local (32-col) row max ----
        float mx0 = -1e30f, mx1 = -1e30f;
#pragma unroll
        for (int nf = 0; nf < 4; nf++) {
            mx0 = fmaxf(mx0, fmaxf(s[nf][0], s[nf][1]));
            mx1 = fmaxf(mx1, fmaxf(s[nf][2], s[nf][3]));
        }
        mx0 = fmaxf(mx0, __shfl_xor_sync(0xffffffffu, mx0, 1));
        mx0 = fmaxf(mx0, __shfl_xor_sync(0xffffffffu, mx0, 2));
        mx1 = fmaxf(mx1, __shfl_xor_sync(0xffffffffu, mx1, 1));
        mx1 = fmaxf(mx1, __shfl_xor_sync(0xffffffffu, mx1, 2));

        // ---- exp relative to local max + local sums ----
        float rs0 = 0.f, rs1 = 0.f;
#pragma unroll
        for (int nf = 0; nf < 4; nf++) {
            s[nf][0] = __expf(s[nf][0] - mx0);
            s[nf][1] = __expf(s[nf][1] - mx0);
            s[nf][2] = __expf(s[nf][2] - mx1);
            s[nf][3] = __expf(s[nf][3] - mx1);
            rs0 += s[nf][0] + s[nf][1];
            rs1 += s[nf][2] + s[nf][3];
        }
        rs0 += __shfl_xor_sync(0xffffffffu, rs0, 1);
        rs0 += __shfl_xor_sync(0xffffffffu, rs0, 2);
        rs1 += __shfl_xor_sync(0xffffffffu, rs1, 1);
        rs1 += __shfl_xor_sync(0xffffffffu, rs1, 2);

        // ---- pairwise merge with the other N-warp ----
        if (tg == 0) {
            Red[r0 * 2 + wn]       = make_float2(mx0, rs0);
            Red[(r0 + 8) * 2 + wn] = make_float2(mx1, rs1);
        }
        asm volatile("bar.sync %0, 64;" :: "r"(1 + wm) : "memory");
        float2 p0 = Red[r0 * 2 + (wn ^ 1)];
        float2 p1 = Red[(r0 + 8) * 2 + (wn ^ 1)];

        float mn0 = fmaxf(m_i[0], fmaxf(mx0, p0.x));
        float mn1 = fmaxf(m_i[1], fmaxf(mx1, p1.x));
        float f0  = __expf(mx0 - mn0);
        float f1  = __expf(mx1 - mn1);
        float al0 = __expf(m_i[0] - mn0);
        float al1 = __expf(m_i[1] - mn1);
        l_i[0] = l_i[0] * al0 + rs0 * f0 + p0.y * __expf(p0.x - mn0);
        l_i[1] = l_i[1] * al1 + rs1 * f1 + p1.y * __expf(p1.x - mn1);
        m_i[0] = mn0;
        m_i[1] = mn1;

#pragma unroll
        for (int nf = 0; nf < 8; nf++) {
            o[nf][0] *= al0; o[nf][1] *= al0;
            o[nf][2] *= al1; o[nf][3] *= al1;
        }

        // ---- stage P (rescaled to global max, RNA-rounded to tf32) ----
#pragma unroll
        for (int nf = 0; nf < 4; nf++) {
            float2 w0 = make_float2(rna_tf32(s[nf][0] * f0), rna_tf32(s[nf][1] * f0));
            float2 w1 = make_float2(rna_tf32(s[nf][2] * f1), rna_tf32(s[nf][3] * f1));
            *(float2*)&Ps[r0 * PSTR + wn * 32 + nf * 8 + tg * 2]       = w0;
            *(float2*)&Ps[(r0 + 8) * PSTR + wn * 32 + nf * 8 + tg * 2] = w1;
        }
        asm volatile("bar.sync %0, 64;" :: "r"(1 + wm) : "memory");

        // ---- O += P . V  (warp: 16 rows x 64 out-cols), single MMA ----
#pragma unroll
        for (int k8 = 0; k8 < 8; k8++) {
            const int k = k8 * 8;
            uint32_t ph[4] = {
                __float_as_uint(Ps[r0 * PSTR + k + tg]),
                __float_as_uint(Ps[(r0 + 8) * PSTR + k + tg]),
                __float_as_uint(Ps[r0 * PSTR + k + tg + 4]),
                __float_as_uint(Ps[(r0 + 8) * PSTR + k + tg + 4])};
#pragma unroll
            for (int nf = 0; nf < 8; nf++) {
                const int col = wn * 64 + nf * 8 + g;
                uint32_t vh[2] = {__float_as_uint(Vh[(k + tg) * VSTR + col]),
                                  __float_as_uint(Vh[(k + tg + 4) * VSTR + col])};
                mma_tf32(o[nf], ph, vh);
            }
        }
    }

    // ---- normalize and store ----
    const float inv0 = 1.f / l_i[0];
    const float inv1 = 1.f / l_i[1];
    const size_t orow = (size_t)b * SEQ + (size_t)qt * ATT_BQ + r0;
#pragma unroll
    for (int nf = 0; nf < 8; nf++) {
        const int col = wn * 64 + nf * 8 + tg * 2;
        *(float2*)&out[orow * HD + col]       = make_float2(o[nf][0] * inv0, o[nf][1] * inv0);
        *(float2*)&out[(orow + 8) * HD + col] = make_float2(o[nf][2] * inv1, o[nf][3] * inv1);
    }
}

// ---------------------------------------------------------------------------
extern "C" void kernel_launch(void* const* d_in, const int* in_sizes, int n_in,
                              void* d_out, int out_size)
{
    const float* x  = (const float*)d_in[0];
    const float* wq = (const float*)d_in[1];
    const float* wk = (const float*)d_in[2];
    const float* wv = (const float*)d_in[3];
    float* out = (float*)d_out;

    cudaFuncSetAttribute(proj_mma_kernel,
                         cudaFuncAttributeMaxDynamicSharedMemorySize, PROJ_SMEM);
    cudaFuncSetAttribute(attn_mma_kernel,
                         cudaFuncAttributeMaxDynamicSharedMemorySize, ATT_SMEM);

    dim3 gridP((BSZ * SEQ) / 128, 3);
    proj_mma_kernel<<<gridP, 256, PROJ_SMEM>>>(x, wq, wk, wv);

    dim3 gridA(SEQ / ATT_BQ, BSZ);
    attn_mma_kernel<<<gridA, 512, ATT_SMEM>>>(out);
}

// round 11
// speedup vs baseline: 1.4564x; 1.1495x over previous
#include <cuda_runtime.h>
#include <math.h>
#include <cstdint>

#define BSZ 16
#define SEQ 2048
#define DIM 1024
#define HD  128

// Scratch for Q, K, V projections — __device__ globals per the no-allocation rule.
__device__ float g_q[BSZ * SEQ * HD];
__device__ float g_k[BSZ * SEQ * HD];
__device__ float g_v[BSZ * SEQ * HD];

// ---------------------------------------------------------------------------
// Helpers
// ---------------------------------------------------------------------------
__device__ __forceinline__ uint32_t smem_u32(const void* p) {
    uint32_t a;
    asm("{ .reg .u64 t; cvta.to.shared.u64 t, %1; cvt.u32.u64 %0, t; }" : "=r"(a) : "l"(p));
    return a;
}

__device__ __forceinline__ void cp16(uint32_t dst, const void* src) {
    asm volatile("cp.async.cg.shared.global [%0], [%1], 16;" :: "r"(dst), "l"(src));
}
#define CP_COMMIT() asm volatile("cp.async.commit_group;" ::: "memory")
template <int N>
__device__ __forceinline__ void cp_wait() {
    asm volatile("cp.async.wait_group %0;" :: "n"(N) : "memory");
}

// RNA round to tf32 (unbiased; keeps value as fp32 with low 13 bits zero)
__device__ __forceinline__ uint32_t f2tf32(float x) {
    uint32_t r;
    asm("cvt.rna.tf32.f32 %0, %1;" : "=r"(r) : "f"(x));
    return r;
}
__device__ __forceinline__ float rna_tf32(float x) {
    return __uint_as_float(f2tf32(x));
}

// HMMA truncates b32 operands to tf32 (top 19 bits). lo = x - trunc(x).
__device__ __forceinline__ float tf32_lo(float x) {
    return x - __uint_as_float(__float_as_uint(x) & 0xFFFFE000u);
}

__device__ __forceinline__ void mma_tf32(float* c, const uint32_t* a, const uint32_t* b) {
    asm volatile(
        "mma.sync.aligned.m16n8k8.row.col.f32.tf32.tf32.f32 "
        "{%0,%1,%2,%3}, {%4,%5,%6,%7}, {%8,%9}, {%0,%1,%2,%3};"
        : "+f"(c[0]), "+f"(c[1]), "+f"(c[2]), "+f"(c[3])
        : "r"(a[0]), "r"(a[1]), "r"(a[2]), "r"(a[3]), "r"(b[0]), "r"(b[1]));
}

// ---------------------------------------------------------------------------
// Projection GEMM via mma.sync tf32, exact-A 2x:  (unchanged from R8/R10 pass)
//   C = (A_raw + A_lo) . rna(B)
// ---------------------------------------------------------------------------
#define A_STRIDE 36
#define B_STRIDE 136
#define A_STAGE_B 18432
#define B_STAGE_B 17408
#define B_BASE_B  (2 * A_STAGE_B)
#define PROJ_SMEM (2 * A_STAGE_B + 2 * B_STAGE_B)
#define PROJ_NT   (DIM / 32)

__global__ __launch_bounds__(256, 2)
void proj_mma_kernel(const float* __restrict__ X,
                     const float* __restrict__ Wq,
                     const float* __restrict__ Wk,
                     const float* __restrict__ Wv)
{
    extern __shared__ float smf[];
    const uint32_t sbase = smem_u32(smf);
    const int tid  = threadIdx.x;
    const int wid  = tid >> 5;
    const int lane = tid & 31;
    const int g    = lane >> 2;
    const int tg   = lane & 3;
    const int wm   = wid >> 1;
    const int wn   = wid & 1;
    const int z    = blockIdx.y;
    const int m0   = blockIdx.x * 128;

    const float* __restrict__ W = (z == 0) ? Wq : ((z == 1) ? Wk : Wv);
    float* __restrict__ C       = (z == 0) ? g_q : ((z == 1) ? g_k : g_v);

    float acc[2][8][4];
#pragma unroll
    for (int mf = 0; mf < 2; mf++)
#pragma unroll
        for (int nf = 0; nf < 8; nf++)
#pragma unroll
            for (int r = 0; r < 4; r++) acc[mf][nf][r] = 0.f;

    auto stage = [&](int s, int t) {
        const int k0 = t * 32;
#pragma unroll
        for (int q = 0; q < 4; q++) {
            int c   = q * 256 + tid;
            int row = c >> 3;
            int ch  = c & 7;
            cp16(sbase + s * A_STAGE_B + row * (A_STRIDE * 4) + ch * 16,
                 &X[(size_t)(m0 + row) * DIM + k0 + ch * 4]);
        }
#pragma unroll
        for (int q = 0; q < 4; q++) {
            int c   = q * 256 + tid;
            int row = c >> 5;
            int ch  = c & 31;
            cp16(sbase + B_BASE_B + s * B_STAGE_B + row * (B_STRIDE * 4) + ch * 16,
                 &W[(size_t)(k0 + row) * HD + ch * 4]);
        }
        CP_COMMIT();
    };

    stage(0, 0);

    for (int t = 0; t < PROJ_NT; t++) {
        const int s = t & 1;
        if (t + 1 < PROJ_NT) {
            stage(s ^ 1, t + 1);
            cp_wait<1>();
        } else {
            cp_wait<0>();
        }
        __syncthreads();

        const float* As = smf + s * (A_STAGE_B / 4);
        const float* Bs = smf + (B_BASE_B / 4) + s * (B_STAGE_B / 4);

#pragma unroll
        for (int sub = 0; sub < 4; sub++) {
            const int k8 = sub * 8;
            uint32_t ah[2][4], al[2][4];
#pragma unroll
            for (int mf = 0; mf < 2; mf++) {
                const int r = wm * 32 + mf * 16 + g;
                float a0 = As[r * A_STRIDE + k8 + tg];
                float a1 = As[(r + 8) * A_STRIDE + k8 + tg];
                float a2 = As[r * A_STRIDE + k8 + tg + 4];
                float a3 = As[(r + 8) * A_STRIDE + k8 + tg + 4];
                ah[mf][0] = __float_as_uint(a0); al[mf][0] = __float_as_uint(tf32_lo(a0));
                ah[mf][1] = __float_as_uint(a1); al[mf][1] = __float_as_uint(tf32_lo(a1));
                ah[mf][2] = __float_as_uint(a2); al[mf][2] = __float_as_uint(tf32_lo(a2));
                ah[mf][3] = __float_as_uint(a3); al[mf][3] = __float_as_uint(tf32_lo(a3));
            }
#pragma unroll
            for (int nf = 0; nf < 8; nf++) {
                const int n = wn * 64 + nf * 8 + g;
                uint32_t bh[2] = {f2tf32(Bs[(k8 + tg) * B_STRIDE + n]),
                                  f2tf32(Bs[(k8 + tg + 4) * B_STRIDE + n])};
#pragma unroll
                for (int mf = 0; mf < 2; mf++) {
                    mma_tf32(acc[mf][nf], ah[mf], bh);
                    mma_tf32(acc[mf][nf], al[mf], bh);
                }
            }
        }
        __syncthreads();
    }

#pragma unroll
    for (int mf = 0; mf < 2; mf++) {
        const int row = m0 + wm * 32 + mf * 16 + g;
#pragma unroll
        for (int nf = 0; nf < 8; nf++) {
            const int col = wn * 64 + nf * 8 + tg * 2;
            *(float2*)&C[(size_t)row * HD + col]       = make_float2(acc[mf][nf][0], acc[mf][nf][1]);
            *(float2*)&C[(size_t)(row + 8) * HD + col] = make_float2(acc[mf][nf][2], acc[mf][nf][3]);
        }
    }
}

// ---------------------------------------------------------------------------
// Flash attention (causal), mma.sync tf32 — R10 numerics, PAIRED scheduling:
// each CTA handles q-tiles (15 - x) and (x): (2(15-x)+2) + (2x+2) = 34
// kv-iterations for every CTA -> 128 identical CTAs, one balanced wave.
// 512 threads, warps as 8M x 2N; Q/K/P/V all RNA-rounded once at smem write,
// all MMA paths single-instruction (pure LDS -> MMA inner loops).
// Smem floats: Qs[128][132] Ks[64][132] Vh[64][136] Ps[128][68] Red
// ---------------------------------------------------------------------------
#define ATT_BQ 128
#define ATT_BK 64
#define QSTR 132
#define KSTR 132
#define VSTR 136
#define PSTR 68
#define QS_OFF 0
#define KS_OFF (ATT_BQ * QSTR)                     // 16896
#define VH_OFF (KS_OFF + ATT_BK * KSTR)            // 25344
#define PS_OFF (VH_OFF + ATT_BK * VSTR)            // 34048
#define RED_OFF (PS_OFF + ATT_BQ * PSTR)           // 42752
#define ATT_SMEM ((RED_OFF + ATT_BQ * 2 * 2) * 4)  // 173056 B

__global__ __launch_bounds__(512, 1)
void attn_mma_kernel(float* __restrict__ out)
{
    extern __shared__ float sm[];
    float* Qs  = sm + QS_OFF;
    float* Ks  = sm + KS_OFF;
    float* Vh  = sm + VH_OFF;
    float* Ps  = sm + PS_OFF;
    float2* Red = (float2*)(sm + RED_OFF);

    const int b    = blockIdx.y;
    const int tid  = threadIdx.x;
    const int lane = tid & 31;
    const int wid  = tid >> 5;
    const int g    = lane >> 2;
    const int tg   = lane & 3;
    const int wm   = wid >> 1;        // 0..7
    const int wn   = wid & 1;         // 0..1
    const int r0   = wm * 16 + g;     // warp row 0 (tile-local)
    const float scale = 0.08838834764831845f;      // 1/sqrt(128)

    const int NQT = SEQ / ATT_BQ;     // 16 q-tiles per batch

    for (int half = 0; half < 2; half++) {
        // pair heavy (15 - x) with light (x): constant total work per CTA
        const int qt = (half == 0) ? (NQT - 1 - blockIdx.x) : blockIdx.x;

        __syncthreads();   // previous half's reads of Qs complete

        // ---- load Q tile (scaled, RNA-rounded once) ----
        const float* __restrict__ Qg = g_q + ((size_t)b * SEQ + (size_t)qt * ATT_BQ) * HD;
#pragma unroll
        for (int t = 0; t < 8; t++) {
            int idx = t * 512 + tid;      // float4 idx over 128x128
            int row = idx >> 5;
            int c4  = (idx & 31) * 4;
            float4 v = *(const float4*)&Qg[(size_t)row * HD + c4];
            v.x = rna_tf32(v.x * scale); v.y = rna_tf32(v.y * scale);
            v.z = rna_tf32(v.z * scale); v.w = rna_tf32(v.w * scale);
            *(float4*)&Qs[row * QSTR + c4] = v;
        }

        float m_i[2] = {-1e30f, -1e30f};
        float l_i[2] = {0.f, 0.f};
        float o[8][4];
#pragma unroll
        for (int nf = 0; nf < 8; nf++)
#pragma unroll
            for (int r = 0; r < 4; r++) o[nf][r] = 0.f;

        const int ntiles = 2 * qt + 2;
        const int rowg   = qt * ATT_BQ + r0;

        for (int j = 0; j < ntiles; j++) {
            const float* __restrict__ Kg = g_k + ((size_t)b * SEQ + (size_t)j * ATT_BK) * HD;
            const float* __restrict__ Vg = g_v + ((size_t)b * SEQ + (size_t)j * ATT_BK) * HD;

            __syncthreads();   // all warps done reading previous Ks/Vh/Ps (and Qs write above)

            // K and V: RNA-round once at fill (MMA truncation is then a no-op)
#pragma unroll
            for (int t = 0; t < 4; t++) {
                int idx = t * 512 + tid;  // float4 idx over 64x128
                int row = idx >> 5;
                int c4  = (idx & 31) * 4;
                float4 kv = *(const float4*)&Kg[(size_t)row * HD + c4];
                kv.x = rna_tf32(kv.x); kv.y = rna_tf32(kv.y);
                kv.z = rna_tf32(kv.z); kv.w = rna_tf32(kv.w);
                *(float4*)&Ks[row * KSTR + c4] = kv;
                float4 v = *(const float4*)&Vg[(size_t)row * HD + c4];
                v.x = rna_tf32(v.x); v.y = rna_tf32(v.y);
                v.z = rna_tf32(v.z); v.w = rna_tf32(v.w);
                *(float4*)&Vh[row * VSTR + c4] = v;
            }
            __syncthreads();

            // ---- S = Q . K^T  (warp: 16 rows x 32 cols), single MMA ----
            float s[4][4];
#pragma unroll
            for (int nf = 0; nf < 4; nf++)
#pragma unroll
                for (int r = 0; r < 4; r++) s[nf][r] = 0.f;

#pragma unroll
            for (int k8 = 0; k8 < 16; k8++) {
                const int k = k8 * 8;
                uint32_t ah[4] = {__float_as_uint(Qs[r0 * QSTR + k + tg]),
                                  __float_as_uint(Qs[(r0 + 8) * QSTR + k + tg]),
                                  __float_as_uint(Qs[r0 * QSTR + k + tg + 4]),
                                  __float_as_uint(Qs[(r0 + 8) * QSTR + k + tg + 4])};
#pragma unroll
                for (int nf = 0; nf < 4; nf++) {
                    const int kr = (wn * 32 + nf * 8 + g) * KSTR + k;
                    uint32_t bh[2] = {__float_as_uint(Ks[kr + tg]),
                                      __float_as_uint(Ks[kr + tg + 4])};
                    mma_tf32(s[nf], ah, bh);
                }
            }

            // ---- causal mask (only last two kv tiles can intersect the diagonal) ----
            if (j >= 2 * qt) {
                const int colbase = j * ATT_BK + wn * 32;
#pragma unroll
                for (int nf = 0; nf < 4; nf++) {
                    int c0 = colbase + nf * 8 + tg * 2;
                    if (c0 > rowg)          s[nf][0] = -1e30f;
                    if (c0 + 1 > rowg)      s[nf][1] = -1e30f;
                    if (c0 > rowg + 8)      s[nf][2] = -1e30f;
                    if (c0 + 1 > rowg + 8)  s[nf][3] = -1e30f;
                }
            }

            // ---- local (32-col) row max ----
            float mx0 = -1e30f, mx1 = -1e30f;
#pragma unroll
            for (int nf = 0; nf < 4; nf++) {
                mx0 = fmaxf(mx0, fmaxf(s[nf][0], s[nf][1]));
                mx1 = fmaxf(mx1, fmaxf(s[nf][2], s[nf][3]));
            }
            mx0 = fmaxf(mx0, __shfl_xor_sync(0xffffffffu, mx0, 1));
            mx0 = fmaxf(mx0, __shfl_xor_sync(0xffffffffu, mx0, 2));
            mx1 = fmaxf(mx1, __shfl_xor_sync(0xffffffffu, mx1, 1));
            mx1 = fmaxf(mx1, __shfl_xor_sync(0xffffffffu, mx1, 2));

            // ---- exp relative to local max + local sums ----
            float rs0 = 0.f, rs1 = 0.f;
#pragma unroll
            for (int nf = 0; nf < 4; nf++) {
                s[nf][0] = __expf(s[nf][0] - mx0);
                s[nf][1] = __expf(s[nf][1] - mx0);
                s[nf][2] = __expf(s[nf][2] - mx1);
                s[nf][3] = __expf(s[nf][3] - mx1);
                rs0 += s[nf][0] + s[nf][1];
                rs1 += s[nf][2] + s[nf][3];
            }
            rs0 += __shfl_xor_sync(0xffffffffu, rs0, 1);
            rs0 += __shfl_xor_sync(0xffffffffu, rs0, 2);
            rs1 += __shfl_xor_sync(0xffffffffu, rs1, 1);
            rs1 += __shfl_xor_sync(0xffffffffu, rs1, 2);

            // ---- pairwise merge with the other N-warp ----
            if (tg == 0) {
                Red[r0 * 2 + wn]       = make_float2(mx0, rs0);
                Red[(r0 + 8) * 2 + wn] = make_float2(mx1, rs1);
            }
            asm volatile("bar.sync %0, 64;" :: "r"(1 + wm) : "memory");
            float2 p0 = Red[r0 * 2 + (wn ^ 1)];
            float2 p1 = Red[(r0 + 8) * 2 + (wn ^ 1)];

            float mn0 = fmaxf(m_i[0], fmaxf(mx0, p0.x));
            float mn1 = fmaxf(m_i[1], fmaxf(mx1, p1.x));
            float f0  = __expf(mx0 - mn0);
            float f1  = __expf(mx1 - mn1);
            float al0 = __expf(m_i[0] - mn0);
            float al1 = __expf(m_i[1] - mn1);
            l_i[0] = l_i[0] * al0 + rs0 * f0 + p0.y * __expf(p0.x - mn0);
            l_i[1] = l_i[1] * al1 + rs1 * f1 + p1.y * __expf(p1.x - mn1);
            m_i[0] = mn0;
            m_i[1] = mn1;

#pragma unroll
            for (int nf = 0; nf < 8; nf++) {
                o[nf][0] *= al0; o[nf][1] *= al0;
                o[nf][2] *= al1; o[nf][3] *= al1;
            }

            // ---- stage P (rescaled to global max, RNA-rounded to tf32) ----
#pragma unroll
            for (int nf = 0; nf < 4; nf++) {
                float2 w0 = make_float2(rna_tf32(s[nf][0] * f0), rna_tf32(s[nf][1] * f0));
                float2 w1 = make_float2(rna_tf32(s[nf][2] * f1), rna_tf32(s[nf][3] * f1));
                *(float2*)&Ps[r0 * PSTR + wn * 32 + nf * 8 + tg * 2]       = w0;
                *(float2*)&Ps[(r0 + 8) * PSTR + wn * 32 + nf * 8 + tg * 2] = w1;
            }
            asm volatile("bar.sync %0, 64;" :: "r"(1 + wm) : "memory");

            // ---- O += P . V  (warp: 16 rows x 64 out-cols), single MMA ----
#pragma unroll
            for (int k8 = 0; k8 < 8; k8++) {
                const int k = k8 * 8;
                uint32_t ph[4] = {
                    __float_as_uint(Ps[r0 * PSTR + k + tg]),
                    __float_as_uint(Ps[(r0 + 8) * PSTR + k + tg]),
                    __float_as_uint(Ps[r0 * PSTR + k + tg + 4]),
                    __float_as_uint(Ps[(r0 + 8) * PSTR + k + tg + 4])};
#pragma unroll
                for (int nf = 0; nf < 8; nf++) {
                    const int col = wn * 64 + nf * 8 + g;
                    uint32_t vh[2] = {__float_as_uint(Vh[(k + tg) * VSTR + col]),
                                      __float_as_uint(Vh[(k + tg + 4) * VSTR + col])};
                    mma_tf32(o[nf], ph, vh);
                }
            }
        }

        // ---- normalize and store ----
        const float inv0 = 1.f / l_i[0];
        const float inv1 = 1.f / l_i[1];
        const size_t orow = (size_t)b * SEQ + (size_t)qt * ATT_BQ + r0;
#pragma unroll
        for (int nf = 0; nf < 8; nf++) {
            const int col = wn * 64 + nf * 8 + tg * 2;
            *(float2*)&out[orow * HD + col]       = make_float2(o[nf][0] * inv0, o[nf][1] * inv0);
            *(float2*)&out[(orow + 8) * HD + col] = make_float2(o[nf][2] * inv1, o[nf][3] * inv1);
        }
    }
}

// ---------------------------------------------------------------------------
extern "C" void kernel_launch(void* const* d_in, const int* in_sizes, int n_in,
                              void* d_out, int out_size)
{
    const float* x  = (const float*)d_in[0];
    const float* wq = (const float*)d_in[1];
    const float* wk = (const float*)d_in[2];
    const float* wv = (const float*)d_in[3];
    float* out = (float*)d_out;

    cudaFuncSetAttribute(proj_mma_kernel,
                         cudaFuncAttributeMaxDynamicSharedMemorySize, PROJ_SMEM);
    cudaFuncSetAttribute(attn_mma_kernel,
                         cudaFuncAttributeMaxDynamicSharedMemorySize, ATT_SMEM);

    dim3 gridP((BSZ * SEQ) / 128, 3);
    proj_mma_kernel<<<gridP, 256, PROJ_SMEM>>>(x, wq, wk, wv);

    dim3 gridA(SEQ / ATT_BQ / 2, BSZ);   // 8 pairs x 16 batches = 128 CTAs
    attn_mma_kernel<<<gridA, 512, ATT_SMEM>>>(out);
}

// round 12
// speedup vs baseline: 1.6921x; 1.1618x over previous
#include <cuda_runtime.h>
#include <math.h>
#include <cstdint>

#define BSZ 16
#define SEQ 2048
#define DIM 1024
#define HD  128

// Scratch for Q, K, V projections — __device__ globals per the no-allocation rule.
__device__ float g_q[BSZ * SEQ * HD];
__device__ float g_k[BSZ * SEQ * HD];
__device__ float g_v[BSZ * SEQ * HD];

// ---------------------------------------------------------------------------
// Helpers
// ---------------------------------------------------------------------------
__device__ __forceinline__ uint32_t smem_u32(const void* p) {
    uint32_t a;
    asm("{ .reg .u64 t; cvta.to.shared.u64 t, %1; cvt.u32.u64 %0, t; }" : "=r"(a) : "l"(p));
    return a;
}

__device__ __forceinline__ void cp16(uint32_t dst, const void* src) {
    asm volatile("cp.async.cg.shared.global [%0], [%1], 16;" :: "r"(dst), "l"(src));
}
#define CP_COMMIT() asm volatile("cp.async.commit_group;" ::: "memory")
template <int N>
__device__ __forceinline__ void cp_wait() {
    asm volatile("cp.async.wait_group %0;" :: "n"(N) : "memory");
}

// RNA round to tf32 (unbiased; keeps value as fp32 with low 13 bits zero)
__device__ __forceinline__ uint32_t f2tf32(float x) {
    uint32_t r;
    asm("cvt.rna.tf32.f32 %0, %1;" : "=r"(r) : "f"(x));
    return r;
}
__device__ __forceinline__ float rna_tf32(float x) {
    return __uint_as_float(f2tf32(x));
}

__device__ __forceinline__ void mma_tf32(float* c, const uint32_t* a, const uint32_t* b) {
    asm volatile(
        "mma.sync.aligned.m16n8k8.row.col.f32.tf32.tf32.f32 "
        "{%0,%1,%2,%3}, {%4,%5,%6,%7}, {%8,%9}, {%0,%1,%2,%3};"
        : "+f"(c[0]), "+f"(c[1]), "+f"(c[2]), "+f"(c[3])
        : "r"(a[0]), "r"(a[1]), "r"(a[2]), "r"(a[3]), "r"(b[0]), "r"(b[1]));
}

// ldmatrix x4: four 8-row x 16B matrices; lane i supplies row ptr of matrix i/8.
#define LDSM_X4(r, a) \
    asm volatile("ldmatrix.sync.aligned.m8n8.x4.shared.b16 {%0,%1,%2,%3}, [%4];" \
        : "=r"((r)[0]), "=r"((r)[1]), "=r"((r)[2]), "=r"((r)[3]) : "r"(a))

// ---------------------------------------------------------------------------
// Projection GEMM via mma.sync tf32, single MMA (both operands RNA-rounded):
//   C = rna(A) . rna(B)
// ---------------------------------------------------------------------------
#define A_STRIDE 36
#define B_STRIDE 136
#define A_STAGE_B 18432
#define B_STAGE_B 17408
#define B_BASE_B  (2 * A_STAGE_B)
#define PROJ_SMEM (2 * A_STAGE_B + 2 * B_STAGE_B)
#define PROJ_NT   (DIM / 32)

__global__ __launch_bounds__(256, 2)
void proj_mma_kernel(const float* __restrict__ X,
                     const float* __restrict__ Wq,
                     const float* __restrict__ Wk,
                     const float* __restrict__ Wv)
{
    extern __shared__ float smf[];
    const uint32_t sbase = smem_u32(smf);
    const int tid  = threadIdx.x;
    const int wid  = tid >> 5;
    const int lane = tid & 31;
    const int g    = lane >> 2;
    const int tg   = lane & 3;
    const int wm   = wid >> 1;
    const int wn   = wid & 1;
    const int z    = blockIdx.y;
    const int m0   = blockIdx.x * 128;

    const float* __restrict__ W = (z == 0) ? Wq : ((z == 1) ? Wk : Wv);
    float* __restrict__ C       = (z == 0) ? g_q : ((z == 1) ? g_k : g_v);

    float acc[2][8][4];
#pragma unroll
    for (int mf = 0; mf < 2; mf++)
#pragma unroll
        for (int nf = 0; nf < 8; nf++)
#pragma unroll
            for (int r = 0; r < 4; r++) acc[mf][nf][r] = 0.f;

    auto stage = [&](int s, int t) {
        const int k0 = t * 32;
#pragma unroll
        for (int q = 0; q < 4; q++) {
            int c   = q * 256 + tid;
            int row = c >> 3;
            int ch  = c & 7;
            cp16(sbase + s * A_STAGE_B + row * (A_STRIDE * 4) + ch * 16,
                 &X[(size_t)(m0 + row) * DIM + k0 + ch * 4]);
        }
#pragma unroll
        for (int q = 0; q < 4; q++) {
            int c   = q * 256 + tid;
            int row = c >> 5;
            int ch  = c & 31;
            cp16(sbase + B_BASE_B + s * B_STAGE_B + row * (B_STRIDE * 4) + ch * 16,
                 &W[(size_t)(k0 + row) * HD + ch * 4]);
        }
        CP_COMMIT();
    };

    stage(0, 0);

    for (int t = 0; t < PROJ_NT; t++) {
        const int s = t & 1;
        if (t + 1 < PROJ_NT) {
            stage(s ^ 1, t + 1);
            cp_wait<1>();
        } else {
            cp_wait<0>();
        }
        __syncthreads();

        const float* As = smf + s * (A_STAGE_B / 4);
        const float* Bs = smf + (B_BASE_B / 4) + s * (B_STAGE_B / 4);

#pragma unroll
        for (int sub = 0; sub < 4; sub++) {
            const int k8 = sub * 8;
            uint32_t ah[2][4];
#pragma unroll
            for (int mf = 0; mf < 2; mf++) {
                const int r = wm * 32 + mf * 16 + g;
                ah[mf][0] = f2tf32(As[r * A_STRIDE + k8 + tg]);
                ah[mf][1] = f2tf32(As[(r + 8) * A_STRIDE + k8 + tg]);
                ah[mf][2] = f2tf32(As[r * A_STRIDE + k8 + tg + 4]);
                ah[mf][3] = f2tf32(As[(r + 8) * A_STRIDE + k8 + tg + 4]);
            }
#pragma unroll
            for (int nf = 0; nf < 8; nf++) {
                const int n = wn * 64 + nf * 8 + g;
                uint32_t bh[2] = {f2tf32(Bs[(k8 + tg) * B_STRIDE + n]),
                                  f2tf32(Bs[(k8 + tg + 4) * B_STRIDE + n])};
#pragma unroll
                for (int mf = 0; mf < 2; mf++)
                    mma_tf32(acc[mf][nf], ah[mf], bh);
            }
        }
        __syncthreads();
    }

#pragma unroll
    for (int mf = 0; mf < 2; mf++) {
        const int row = m0 + wm * 32 + mf * 16 + g;
#pragma unroll
        for (int nf = 0; nf < 8; nf++) {
            const int col = wn * 64 + nf * 8 + tg * 2;
            *(float2*)&C[(size_t)row * HD + col]       = make_float2(acc[mf][nf][0], acc[mf][nf][1]);
            *(float2*)&C[(size_t)(row + 8) * HD + col] = make_float2(acc[mf][nf][2], acc[mf][nf][3]);
        }
    }
}

// ---------------------------------------------------------------------------
// Flash attention (causal), mma.sync tf32 — R11 numerics + paired scheduling,
// fragment loads via ldmatrix.x4 (one instr per A-frag, one per 2 B-frags).
// V stored TRANSPOSED in smem (Vt[h][kv], stride 68) so PV B-frags use
// non-trans ldmatrix. All operands RNA-rounded once; single-MMA paths.
// Smem floats: Qs[128][132] Ks[64][132] Vt[128][68] Ps[128][68] Red
// ---------------------------------------------------------------------------
#define ATT_BQ 128
#define ATT_BK 64
#define QSTR 132
#define KSTR 132
#define VTSTR 68
#define PSTR 68
#define QS_OFF 0
#define KS_OFF (ATT_BQ * QSTR)                     // 16896
#define VT_OFF (KS_OFF + ATT_BK * KSTR)            // 25344
#define PS_OFF (VT_OFF + HD * VTSTR)               // 34048
#define RED_OFF (PS_OFF + ATT_BQ * PSTR)           // 42752
#define ATT_SMEM ((RED_OFF + ATT_BQ * 2 * 2) * 4)  // 173056 B

__global__ __launch_bounds__(512, 1)
void attn_mma_kernel(float* __restrict__ out)
{
    extern __shared__ float sm[];
    float* Qs  = sm + QS_OFF;
    float* Ks  = sm + KS_OFF;
    float* Vt  = sm + VT_OFF;
    float* Ps  = sm + PS_OFF;
    float2* Red = (float2*)(sm + RED_OFF);
    const uint32_t sbase = smem_u32(sm);

    const int b    = blockIdx.y;
    const int tid  = threadIdx.x;
    const int lane = tid & 31;
    const int wid  = tid >> 5;
    const int g    = lane >> 2;
    const int tg   = lane & 3;
    const int wm   = wid >> 1;        // 0..7
    const int wn   = wid & 1;         // 0..1
    const int wbase = wm * 16;
    const int r0   = wbase + g;       // warp row 0 (tile-local)
    const float scale = 0.08838834764831845f;      // 1/sqrt(128)

    // ---- ldmatrix per-lane base addresses (bytes) ----
    // A-frag (Qs/Ps): rows wbase + (lane&15), col offset (lane>>4)*4
    const int rA = lane & 15;
    const int cA = (lane >> 4) * 4;
    const uint32_t q_base = sbase + (uint32_t)(QS_OFF + (wbase + rA) * QSTR + cA) * 4;
    const uint32_t p_base = sbase + (uint32_t)(PS_OFF + (wbase + rA) * PSTR + cA) * 4;
    // B-frag pair: rows base + (lane&7) + ((lane>>4)<<3), col ((lane>>3)&1)*4
    const int rB = (lane & 7) + ((lane >> 4) << 3);
    const int cB = ((lane >> 3) & 1) * 4;
    const uint32_t k_base0 = sbase + (uint32_t)(KS_OFF + (wn * 32 + rB) * KSTR + cB) * 4;
    const uint32_t k_base1 = sbase + (uint32_t)(KS_OFF + (wn * 32 + 16 + rB) * KSTR + cB) * 4;
    uint32_t v_base[4];
#pragma unroll
    for (int p = 0; p < 4; p++)
        v_base[p] = sbase + (uint32_t)(VT_OFF + (wn * 64 + p * 16 + rB) * VTSTR + cB) * 4;

    const int NQT = SEQ / ATT_BQ;     // 16 q-tiles per batch

    for (int half = 0; half < 2; half++) {
        const int qt = (half == 0) ? (NQT - 1 - blockIdx.x) : blockIdx.x;

        __syncthreads();   // previous half's reads of Qs complete

        // ---- load Q tile (scaled, RNA-rounded once) ----
        const float* __restrict__ Qg = g_q + ((size_t)b * SEQ + (size_t)qt * ATT_BQ) * HD;
#pragma unroll
        for (int t = 0; t < 8; t++) {
            int idx = t * 512 + tid;
            int row = idx >> 5;
            int c4  = (idx & 31) * 4;
            float4 v = *(const float4*)&Qg[(size_t)row * HD + c4];
            v.x = rna_tf32(v.x * scale); v.y = rna_tf32(v.y * scale);
            v.z = rna_tf32(v.z * scale); v.w = rna_tf32(v.w * scale);
            *(float4*)&Qs[row * QSTR + c4] = v;
        }

        float m_i[2] = {-1e30f, -1e30f};
        float l_i[2] = {0.f, 0.f};
        float o[8][4];
#pragma unroll
        for (int nf = 0; nf < 8; nf++)
#pragma unroll
            for (int r = 0; r < 4; r++) o[nf][r] = 0.f;

        const int ntiles = 2 * qt + 2;
        const int rowg   = qt * ATT_BQ + r0;

        for (int j = 0; j < ntiles; j++) {
            const float* __restrict__ Kg = g_k + ((size_t)b * SEQ + (size_t)j * ATT_BK) * HD;
            const float* __restrict__ Vg = g_v + ((size_t)b * SEQ + (size_t)j * ATT_BK) * HD;

            __syncthreads();   // all warps done reading previous Ks/Vt/Ps

            // K: row-major, RNA-rounded
#pragma unroll
            for (int t = 0; t < 4; t++) {
                int idx = t * 512 + tid;
                int row = idx >> 5;
                int c4  = (idx & 31) * 4;
                float4 kv = *(const float4*)&Kg[(size_t)row * HD + c4];
                kv.x = rna_tf32(kv.x); kv.y = rna_tf32(kv.y);
                kv.z = rna_tf32(kv.z); kv.w = rna_tf32(kv.w);
                *(float4*)&Ks[row * KSTR + c4] = kv;
            }
            // V: TRANSPOSED (Vt[h][kv]), RNA-rounded; STS conflict-free (lane = kv row)
#pragma unroll
            for (int it = 0; it < 2; it++)
#pragma unroll
                for (int jt = 0; jt < 2; jt++) {
                    int row = it * 32 + lane;            // kv row
                    int c4  = (wid + jt * 16) * 4;       // head col base
                    float4 v = *(const float4*)&Vg[(size_t)row * HD + c4];
                    Vt[(c4 + 0) * VTSTR + row] = rna_tf32(v.x);
                    Vt[(c4 + 1) * VTSTR + row] = rna_tf32(v.y);
                    Vt[(c4 + 2) * VTSTR + row] = rna_tf32(v.z);
                    Vt[(c4 + 3) * VTSTR + row] = rna_tf32(v.w);
                }
            __syncthreads();

            // ---- S = Q . K^T  (warp: 16 rows x 32 cols) via ldmatrix ----
            float s[4][4];
#pragma unroll
            for (int nf = 0; nf < 4; nf++)
#pragma unroll
                for (int r = 0; r < 4; r++) s[nf][r] = 0.f;

#pragma unroll
            for (int k8 = 0; k8 < 16; k8++) {
                const uint32_t koff = k8 * 32;   // 8 floats = 32 bytes
                uint32_t ah[4], bb[4];
                LDSM_X4(ah, q_base + koff);
                LDSM_X4(bb, k_base0 + koff);
                mma_tf32(s[0], ah, bb);
                mma_tf32(s[1], ah, bb + 2);
                LDSM_X4(bb, k_base1 + koff);
                mma_tf32(s[2], ah, bb);
                mma_tf32(s[3], ah, bb + 2);
            }

            // ---- causal mask (only last two kv tiles can intersect diagonal) ----
            if (j >= 2 * qt) {
                const int colbase = j * ATT_BK + wn * 32;
#pragma unroll
                for (int nf = 0; nf < 4; nf++) {
                    int c0 = colbase + nf * 8 + tg * 2;
                    if (c0 > rowg)          s[nf][0] = -1e30f;
                    if (c0 + 1 > rowg)      s[nf][1] = -1e30f;
                    if (c0 > rowg + 8)      s[nf][2] = -1e30f;
                    if (c0 + 1 > rowg + 8)  s[nf][3] = -1e30f;
                }
            }

            // ---- local (32-col) row max ----
            float mx0 = -1e30f, mx1 = -1e30f;
#pragma unroll
            for (int nf = 0; nf < 4; nf++) {
                mx0 = fmaxf(mx0, fmaxf(s[nf][0], s[nf][1]));
                mx1 = fmaxf(mx1, fmaxf(s[nf][2], s[nf][3]));
            }
            mx0 = fmaxf(mx0, __shfl_xor_sync(0xffffffffu, mx0, 1));
            mx0 = fmaxf(mx0, __shfl_xor_sync(0xffffffffu, mx0, 2));
            mx1 = fmaxf(mx1, __shfl_xor_sync(0xffffffffu, mx1, 1));
            mx1 = fmaxf(mx1, __shfl_xor_sync(0xffffffffu, mx1, 2));

            // ---- exp relative to local max + local sums ----
            float rs0 = 0.f, rs1 = 0.f;
#pragma unroll
            for (int nf = 0; nf < 4; nf++) {
                s[nf][0] = __expf(s[nf][0] - mx0);
                s[nf][1] = __expf(s[nf][1] - mx0);
                s[nf][2] = __expf(s[nf][2] - mx1);
                s[nf][3] = __expf(s[nf][3] - mx1);
                rs0 += s[nf][0] + s[nf][1];
                rs1 += s[nf][2] + s[nf][3];
            }
            rs0 += __shfl_xor_sync(0xffffffffu, rs0, 1);
            rs0 += __shfl_xor_sync(0xffffffffu, rs0, 2);
            rs1 += __shfl_xor_sync(0xffffffffu, rs1, 1);
            rs1 += __shfl_xor_sync(0xffffffffu, rs1, 2);

            // ---- pairwise merge with the other N-warp ----
            if (tg == 0) {
                Red[r0 * 2 + wn]       = make_float2(mx0, rs0);
                Red[(r0 + 8) * 2 + wn] = make_float2(mx1, rs1);
            }
            asm volatile("bar.sync %0, 64;" :: "r"(1 + wm) : "memory");
            float2 p0 = Red[r0 * 2 + (wn ^ 1)];
            float2 p1 = Red[(r0 + 8) * 2 + (wn ^ 1)];

            float mn0 = fmaxf(m_i[0], fmaxf(mx0, p0.x));
            float mn1 = fmaxf(m_i[1], fmaxf(mx1, p1.x));
            float f0  = __expf(mx0 - mn0);
            float f1  = __expf(mx1 - mn1);
            float al0 = __expf(m_i[0] - mn0);
            float al1 = __expf(m_i[1] - mn1);
            l_i[0] = l_i[0] * al0 + rs0 * f0 + p0.y * __expf(p0.x - mn0);
            l_i[1] = l_i[1] * al1 + rs1 * f1 + p1.y * __expf(p1.x - mn1);
            m_i[0] = mn0;
            m_i[1] = mn1;

#pragma unroll
            for (int nf = 0; nf < 8; nf++) {
                o[nf][0] *= al0; o[nf][1] *= al0;
                o[nf][2] *= al1; o[nf][3] *= al1;
            }

            // ---- stage P (rescaled to global max, RNA-rounded to tf32) ----
#pragma unroll
            for (int nf = 0; nf < 4; nf++) {
                float2 w0 = make_float2(rna_tf32(s[nf][0] * f0), rna_tf32(s[nf][1] * f0));
                float2 w1 = make_float2(rna_tf32(s[nf][2] * f1), rna_tf32(s[nf][3] * f1));
                *(float2*)&Ps[r0 * PSTR + wn * 32 + nf * 8 + tg * 2]       = w0;
                *(float2*)&Ps[(r0 + 8) * PSTR + wn * 32 + nf * 8 + tg * 2] = w1;
            }
            asm volatile("bar.sync %0, 64;" :: "r"(1 + wm) : "memory");

            // ---- O += P . V  (warp: 16 rows x 64 out-cols) via ldmatrix ----
#pragma unroll
            for (int k8 = 0; k8 < 8; k8++) {
                const uint32_t koff = k8 * 32;
                uint32_t ph[4];
                LDSM_X4(ph, p_base + koff);
#pragma unroll
                for (int p = 0; p < 4; p++) {
                    uint32_t vv[4];
                    LDSM_X4(vv, v_base[p] + koff);
                    mma_tf32(o[2 * p],     ph, vv);
                    mma_tf32(o[2 * p + 1], ph, vv + 2);
                }
            }
        }

        // ---- normalize and store ----
        const float inv0 = 1.f / l_i[0];
        const float inv1 = 1.f / l_i[1];
        const size_t orow = (size_t)b * SEQ + (size_t)qt * ATT_BQ + r0;
#pragma unroll
        for (int nf = 0; nf < 8; nf++) {
            const int col = wn * 64 + nf * 8 + tg * 2;
            *(float2*)&out[orow * HD + col]       = make_float2(o[nf][0] * inv0, o[nf][1] * inv0);
            *(float2*)&out[(orow + 8) * HD + col] = make_float2(o[nf][2] * inv1, o[nf][3] * inv1);
        }
    }
}

// ---------------------------------------------------------------------------
extern "C" void kernel_launch(void* const* d_in, const int* in_sizes, int n_in,
                              void* d_out, int out_size)
{
    const float* x  = (const float*)d_in[0];
    const float* wq = (const float*)d_in[1];
    const float* wk = (const float*)d_in[2];
    const float* wv = (const float*)d_in[3];
    float* out = (float*)d_out;

    cudaFuncSetAttribute(proj_mma_kernel,
                         cudaFuncAttributeMaxDynamicSharedMemorySize, PROJ_SMEM);
    cudaFuncSetAttribute(attn_mma_kernel,
                         cudaFuncAttributeMaxDynamicSharedMemorySize, ATT_SMEM);

    dim3 gridP((BSZ * SEQ) / 128, 3);
    proj_mma_kernel<<<gridP, 256, PROJ_SMEM>>>(x, wq, wk, wv);

    dim3 gridA(SEQ / ATT_BQ / 2, BSZ);   // 8 pairs x 16 batches = 128 CTAs
    attn_mma_kernel<<<gridA, 512, ATT_SMEM>>>(out);
}

// round 13
// speedup vs baseline: 1.8340x; 1.0839x over previous
#include <cuda_runtime.h>
#include <math.h>
#include <cstdint>

#define BSZ 16
#define SEQ 2048
#define DIM 1024
#define HD  128

// Scratch for Q, K, V projections — __device__ globals per the no-allocation rule.
__device__ float g_q[BSZ * SEQ * HD];
__device__ float g_k[BSZ * SEQ * HD];
__device__ float g_v[BSZ * SEQ * HD];

// ---------------------------------------------------------------------------
// Helpers
// ---------------------------------------------------------------------------
__device__ __forceinline__ uint32_t smem_u32(const void* p) {
    uint32_t a;
    asm("{ .reg .u64 t; cvta.to.shared.u64 t, %1; cvt.u32.u64 %0, t; }" : "=r"(a) : "l"(p));
    return a;
}

__device__ __forceinline__ void cp16(uint32_t dst, const void* src) {
    asm volatile("cp.async.cg.shared.global [%0], [%1], 16;" :: "r"(dst), "l"(src));
}
#define CP_COMMIT() asm volatile("cp.async.commit_group;" ::: "memory")
template <int N>
__device__ __forceinline__ void cp_wait() {
    asm volatile("cp.async.wait_group %0;" :: "n"(N) : "memory");
}

// RNA round to tf32 (unbiased; keeps value as fp32 with low 13 bits zero)
__device__ __forceinline__ uint32_t f2tf32(float x) {
    uint32_t r;
    asm("cvt.rna.tf32.f32 %0, %1;" : "=r"(r) : "f"(x));
    return r;
}
__device__ __forceinline__ float rna_tf32(float x) {
    return __uint_as_float(f2tf32(x));
}

__device__ __forceinline__ void mma_tf32(float* c, const uint32_t* a, const uint32_t* b) {
    asm volatile(
        "mma.sync.aligned.m16n8k8.row.col.f32.tf32.tf32.f32 "
        "{%0,%1,%2,%3}, {%4,%5,%6,%7}, {%8,%9}, {%0,%1,%2,%3};"
        : "+f"(c[0]), "+f"(c[1]), "+f"(c[2]), "+f"(c[3])
        : "r"(a[0]), "r"(a[1]), "r"(a[2]), "r"(a[3]), "r"(b[0]), "r"(b[1]));
}

// ldmatrix x4: four 8-row x 16B matrices; lane i supplies row ptr of matrix i/8.
#define LDSM_X4(r, a) \
    asm volatile("ldmatrix.sync.aligned.m8n8.x4.shared.b16 {%0,%1,%2,%3}, [%4];" \
        : "=r"((r)[0]), "=r"((r)[1]), "=r"((r)[2]), "=r"((r)[3]) : "r"(a))

// ---------------------------------------------------------------------------
// Projection GEMM via mma.sync tf32, single MMA (both operands RNA-rounded):
//   C = rna(A) . rna(B)          (unchanged from R12 pass — 194 us)
// ---------------------------------------------------------------------------
#define A_STRIDE 36
#define B_STRIDE 136
#define A_STAGE_B 18432
#define B_STAGE_B 17408
#define B_BASE_B  (2 * A_STAGE_B)
#define PROJ_SMEM (2 * A_STAGE_B + 2 * B_STAGE_B)
#define PROJ_NT   (DIM / 32)

__global__ __launch_bounds__(256, 2)
void proj_mma_kernel(const float* __restrict__ X,
                     const float* __restrict__ Wq,
                     const float* __restrict__ Wk,
                     const float* __restrict__ Wv)
{
    extern __shared__ float smf[];
    const uint32_t sbase = smem_u32(smf);
    const int tid  = threadIdx.x;
    const int wid  = tid >> 5;
    const int lane = tid & 31;
    const int g    = lane >> 2;
    const int tg   = lane & 3;
    const int wm   = wid >> 1;
    const int wn   = wid & 1;
    const int z    = blockIdx.y;
    const int m0   = blockIdx.x * 128;

    const float* __restrict__ W = (z == 0) ? Wq : ((z == 1) ? Wk : Wv);
    float* __restrict__ C       = (z == 0) ? g_q : ((z == 1) ? g_k : g_v);

    float acc[2][8][4];
#pragma unroll
    for (int mf = 0; mf < 2; mf++)
#pragma unroll
        for (int nf = 0; nf < 8; nf++)
#pragma unroll
            for (int r = 0; r < 4; r++) acc[mf][nf][r] = 0.f;

    auto stage = [&](int s, int t) {
        const int k0 = t * 32;
#pragma unroll
        for (int q = 0; q < 4; q++) {
            int c   = q * 256 + tid;
            int row = c >> 3;
            int ch  = c & 7;
            cp16(sbase + s * A_STAGE_B + row * (A_STRIDE * 4) + ch * 16,
                 &X[(size_t)(m0 + row) * DIM + k0 + ch * 4]);
        }
#pragma unroll
        for (int q = 0; q < 4; q++) {
            int c   = q * 256 + tid;
            int row = c >> 5;
            int ch  = c & 31;
            cp16(sbase + B_BASE_B + s * B_STAGE_B + row * (B_STRIDE * 4) + ch * 16,
                 &W[(size_t)(k0 + row) * HD + ch * 4]);
        }
        CP_COMMIT();
    };

    stage(0, 0);

    for (int t = 0; t < PROJ_NT; t++) {
        const int s = t & 1;
        if (t + 1 < PROJ_NT) {
            stage(s ^ 1, t + 1);
            cp_wait<1>();
        } else {
            cp_wait<0>();
        }
        __syncthreads();

        const float* As = smf + s * (A_STAGE_B / 4);
        const float* Bs = smf + (B_BASE_B / 4) + s * (B_STAGE_B / 4);

#pragma unroll
        for (int sub = 0; sub < 4; sub++) {
            const int k8 = sub * 8;
            uint32_t ah[2][4];
#pragma unroll
            for (int mf = 0; mf < 2; mf++) {
                const int r = wm * 32 + mf * 16 + g;
                ah[mf][0] = f2tf32(As[r * A_STRIDE + k8 + tg]);
                ah[mf][1] = f2tf32(As[(r + 8) * A_STRIDE + k8 + tg]);
                ah[mf][2] = f2tf32(As[r * A_STRIDE + k8 + tg + 4]);
                ah[mf][3] = f2tf32(As[(r + 8) * A_STRIDE + k8 + tg + 4]);
            }
#pragma unroll
            for (int nf = 0; nf < 8; nf++) {
                const int n = wn * 64 + nf * 8 + g;
                uint32_t bh[2] = {f2tf32(Bs[(k8 + tg) * B_STRIDE + n]),
                                  f2tf32(Bs[(k8 + tg + 4) * B_STRIDE + n])};
#pragma unroll
                for (int mf = 0; mf < 2; mf++)
                    mma_tf32(acc[mf][nf], ah[mf], bh);
            }
        }
        __syncthreads();
    }

#pragma unroll
    for (int mf = 0; mf < 2; mf++) {
        const int row = m0 + wm * 32 + mf * 16 + g;
#pragma unroll
        for (int nf = 0; nf < 8; nf++) {
            const int col = wn * 64 + nf * 8 + tg * 2;
            *(float2*)&C[(size_t)row * HD + col]       = make_float2(acc[mf][nf][0], acc[mf][nf][1]);
            *(float2*)&C[(size_t)(row + 8) * HD + col] = make_float2(acc[mf][nf][2], acc[mf][nf][3]);
        }
    }
}

// ---------------------------------------------------------------------------
// Flash attention (causal), mma.sync tf32 — R11 structure (row-major V, float4
// fills, paired scheduling) + ldmatrix ONLY on row-major operands (Q, K, P).
// V stays row-major; PV loads V fragments with scalar LDS (R11 path).
// All operands RNA-rounded once; single-MMA paths.
// Smem floats: Qs[128][132] Ks[64][132] Vh[64][136] Ps[128][68] Red
// ---------------------------------------------------------------------------
#define ATT_BQ 128
#define ATT_BK 64
#define QSTR 132
#define KSTR 132
#define VSTR 136
#define PSTR 68
#define QS_OFF 0
#define KS_OFF (ATT_BQ * QSTR)                     // 16896
#define VH_OFF (KS_OFF + ATT_BK * KSTR)            // 25344
#define PS_OFF (VH_OFF + ATT_BK * VSTR)            // 34048
#define RED_OFF (PS_OFF + ATT_BQ * PSTR)           // 42752
#define ATT_SMEM ((RED_OFF + ATT_BQ * 2 * 2) * 4)  // 173056 B

__global__ __launch_bounds__(512, 1)
void attn_mma_kernel(float* __restrict__ out)
{
    extern __shared__ float sm[];
    float* Qs  = sm + QS_OFF;
    float* Ks  = sm + KS_OFF;
    float* Vh  = sm + VH_OFF;
    float* Ps  = sm + PS_OFF;
    float2* Red = (float2*)(sm + RED_OFF);
    const uint32_t sbase = smem_u32(sm);

    const int b    = blockIdx.y;
    const int tid  = threadIdx.x;
    const int lane = tid & 31;
    const int wid  = tid >> 5;
    const int g    = lane >> 2;
    const int tg   = lane & 3;
    const int wm   = wid >> 1;        // 0..7
    const int wn   = wid & 1;         // 0..1
    const int wbase = wm * 16;
    const int r0   = wbase + g;       // warp row 0 (tile-local)
    const float scale = 0.08838834764831845f;      // 1/sqrt(128)

    // ---- ldmatrix per-lane base addresses (bytes) ----
    // A-frag (Qs/Ps): rows wbase + (lane&15), col offset (lane>>4)*4 floats
    const int rA = lane & 15;
    const int cA = (lane >> 4) * 4;
    const uint32_t q_base = sbase + (uint32_t)(QS_OFF + (wbase + rA) * QSTR + cA) * 4;
    const uint32_t p_base = sbase + (uint32_t)(PS_OFF + (wbase + rA) * PSTR + cA) * 4;
    // B-frag pair (Ks): rows base + (lane&7) + ((lane>>4)<<3), col ((lane>>3)&1)*4
    const int rB = (lane & 7) + ((lane >> 4) << 3);
    const int cB = ((lane >> 3) & 1) * 4;
    const uint32_t k_base0 = sbase + (uint32_t)(KS_OFF + (wn * 32 + rB) * KSTR + cB) * 4;
    const uint32_t k_base1 = sbase + (uint32_t)(KS_OFF + (wn * 32 + 16 + rB) * KSTR + cB) * 4;

    const int NQT = SEQ / ATT_BQ;     // 16 q-tiles per batch

    for (int half = 0; half < 2; half++) {
        const int qt = (half == 0) ? (NQT - 1 - blockIdx.x) : blockIdx.x;

        __syncthreads();   // previous half's reads of Qs complete

        // ---- load Q tile (scaled, RNA-rounded once) ----
        const float* __restrict__ Qg = g_q + ((size_t)b * SEQ + (size_t)qt * ATT_BQ) * HD;
#pragma unroll
        for (int t = 0; t < 8; t++) {
            int idx = t * 512 + tid;
            int row = idx >> 5;
            int c4  = (idx & 31) * 4;
            float4 v = *(const float4*)&Qg[(size_t)row * HD + c4];
            v.x = rna_tf32(v.x * scale); v.y = rna_tf32(v.y * scale);
            v.z = rna_tf32(v.z * scale); v.w = rna_tf32(v.w * scale);
            *(float4*)&Qs[row * QSTR + c4] = v;
        }

        float m_i[2] = {-1e30f, -1e30f};
        float l_i[2] = {0.f, 0.f};
        float o[8][4];
#pragma unroll
        for (int nf = 0; nf < 8; nf++)
#pragma unroll
            for (int r = 0; r < 4; r++) o[nf][r] = 0.f;

        const int ntiles = 2 * qt + 2;
        const int rowg   = qt * ATT_BQ + r0;

        for (int j = 0; j < ntiles; j++) {
            const float* __restrict__ Kg = g_k + ((size_t)b * SEQ + (size_t)j * ATT_BK) * HD;
            const float* __restrict__ Vg = g_v + ((size_t)b * SEQ + (size_t)j * ATT_BK) * HD;

            __syncthreads();   // all warps done reading previous Ks/Vh/Ps

            // K and V: row-major, RNA-rounded, float4 fills (R11 path)
#pragma unroll
            for (int t = 0; t < 4; t++) {
                int idx = t * 512 + tid;
                int row = idx >> 5;
                int c4  = (idx & 31) * 4;
                float4 kv = *(const float4*)&Kg[(size_t)row * HD + c4];
                kv.x = rna_tf32(kv.x); kv.y = rna_tf32(kv.y);
                kv.z = rna_tf32(kv.z); kv.w = rna_tf32(kv.w);
                *(float4*)&Ks[row * KSTR + c4] = kv;
                float4 v = *(const float4*)&Vg[(size_t)row * HD + c4];
                v.x = rna_tf32(v.x); v.y = rna_tf32(v.y);
                v.z = rna_tf32(v.z); v.w = rna_tf32(v.w);
                *(float4*)&Vh[row * VSTR + c4] = v;
            }
            __syncthreads();

            // ---- S = Q . K^T  (warp: 16 rows x 32 cols) via ldmatrix ----
            float s[4][4];
#pragma unroll
            for (int nf = 0; nf < 4; nf++)
#pragma unroll
                for (int r = 0; r < 4; r++) s[nf][r] = 0.f;

#pragma unroll
            for (int k8 = 0; k8 < 16; k8++) {
                const uint32_t koff = k8 * 32;   // 8 floats = 32 bytes
                uint32_t ah[4], bb[4];
                LDSM_X4(ah, q_base + koff);
                LDSM_X4(bb, k_base0 + koff);
                mma_tf32(s[0], ah, bb);
                mma_tf32(s[1], ah, bb + 2);
                LDSM_X4(bb, k_base1 + koff);
                mma_tf32(s[2], ah, bb);
                mma_tf32(s[3], ah, bb + 2);
            }

            // ---- causal mask (only last two kv tiles can intersect diagonal) ----
            if (j >= 2 * qt) {
                const int colbase = j * ATT_BK + wn * 32;
#pragma unroll
                for (int nf = 0; nf < 4; nf++) {
                    int c0 = colbase + nf * 8 + tg * 2;
                    if (c0 > rowg)          s[nf][0] = -1e30f;
                    if (c0 + 1 > rowg)      s[nf][1] = -1e30f;
                    if (c0 > rowg + 8)      s[nf][2] = -1e30f;
                    if (c0 + 1 > rowg + 8)  s[nf][3] = -1e30f;
                }
            }

            // ---- local (32-col) row max ----
            float mx0 = -1e30f, mx1 = -1e30f;
#pragma unroll
            for (int nf = 0; nf < 4; nf++) {
                mx0 = fmaxf(mx0, fmaxf(s[nf][0], s[nf][1]));
                mx1 = fmaxf(mx1, fmaxf(s[nf][2], s[nf][3]));
            }
            mx0 = fmaxf(mx0, __shfl_xor_sync(0xffffffffu, mx0, 1));
            mx0 = fmaxf(mx0, __shfl_xor_sync(0xffffffffu, mx0, 2));
            mx1 = fmaxf(mx1, __shfl_xor_sync(0xffffffffu, mx1, 1));
            mx1 = fmaxf(mx1, __shfl_xor_sync(0xffffffffu, mx1, 2));

            // ---- exp relative to local max + local sums ----
            float rs0 = 0.f, rs1 = 0.f;
#pragma unroll
            for (int nf = 0; nf < 4; nf++) {
                s[nf][0] = __expf(s[nf][0] - mx0);
                s[nf][1] = __expf(s[nf][1] - mx0);
                s[nf][2] = __expf(s[nf][2] - mx1);
                s[nf][3] = __expf(s[nf][3] - mx1);
                rs0 += s[nf][0] + s[nf][1];
                rs1 += s[nf][2] + s[nf][3];
            }
            rs0 += __shfl_xor_sync(0xffffffffu, rs0, 1);
            rs0 += __shfl_xor_sync(0xffffffffu, rs0, 2);
            rs1 += __shfl_xor_sync(0xffffffffu, rs1, 1);
            rs1 += __shfl_xor_sync(0xffffffffu, rs1, 2);

            // ---- pairwise merge with the other N-warp ----
            if (tg == 0) {
                Red[r0 * 2 + wn]       = make_float2(mx0, rs0);
                Red[(r0 + 8) * 2 + wn] = make_float2(mx1, rs1);
            }
            asm volatile("bar.sync %0, 64;" :: "r"(1 + wm) : "memory");
            float2 p0 = Red[r0 * 2 + (wn ^ 1)];
            float2 p1 = Red[(r0 + 8) * 2 + (wn ^ 1)];

            float mn0 = fmaxf(m_i[0], fmaxf(mx0, p0.x));
            float mn1 = fmaxf(m_i[1], fmaxf(mx1, p1.x));
            float f0  = __expf(mx0 - mn0);
            float f1  = __expf(mx1 - mn1);
            float al0 = __expf(m_i[0] - mn0);
            float al1 = __expf(m_i[1] - mn1);
            l_i[0] = l_i[0] * al0 + rs0 * f0 + p0.y * __expf(p0.x - mn0);
            l_i[1] = l_i[1] * al1 + rs1 * f1 + p1.y * __expf(p1.x - mn1);
            m_i[0] = mn0;
            m_i[1] = mn1;

#pragma unroll
            for (int nf = 0; nf < 8; nf++) {
                o[nf][0] *= al0; o[nf][1] *= al0;
                o[nf][2] *= al1; o[nf][3] *= al1;
            }

            // ---- stage P (rescaled to global max, RNA-rounded to tf32) ----
#pragma unroll
            for (int nf = 0; nf < 4; nf++) {
                float2 w0 = make_float2(rna_tf32(s[nf][0] * f0), rna_tf32(s[nf][1] * f0));
                float2 w1 = make_float2(rna_tf32(s[nf][2] * f1), rna_tf32(s[nf][3] * f1));
                *(float2*)&Ps[r0 * PSTR + wn * 32 + nf * 8 + tg * 2]       = w0;
                *(float2*)&Ps[(r0 + 8) * PSTR + wn * 32 + nf * 8 + tg * 2] = w1;
            }
            asm volatile("bar.sync %0, 64;" :: "r"(1 + wm) : "memory");

            // ---- O += P . V  (warp: 16 rows x 64 out-cols) ----
            // P fragment via ldmatrix; V fragments via scalar LDS (row-major)
#pragma unroll
            for (int k8 = 0; k8 < 8; k8++) {
                const int k = k8 * 8;
                uint32_t ph[4];
                LDSM_X4(ph, p_base + (uint32_t)(k8 * 32));
#pragma unroll
                for (int nf = 0; nf < 8; nf++) {
                    const int col = wn * 64 + nf * 8 + g;
                    uint32_t vh[2] = {__float_as_uint(Vh[(k + tg) * VSTR + col]),
                                      __float_as_uint(Vh[(k + tg + 4) * VSTR + col])};
                    mma_tf32(o[nf], ph, vh);
                }
            }
        }

        // ---- normalize and store ----
        const float inv0 = 1.f / l_i[0];
        const float inv1 = 1.f / l_i[1];
        const size_t orow = (size_t)b * SEQ + (size_t)qt * ATT_BQ + r0;
#pragma unroll
        for (int nf = 0; nf < 8; nf++) {
            const int col = wn * 64 + nf * 8 + tg * 2;
            *(float2*)&out[orow * HD + col]       = make_float2(o[nf][0] * inv0, o[nf][1] * inv0);
            *(float2*)&out[(orow + 8) * HD + col] = make_float2(o[nf][2] * inv1, o[nf][3] * inv1);
        }
    }
}

// ---------------------------------------------------------------------------
extern "C" void kernel_launch(void* const* d_in, const int* in_sizes, int n_in,
                              void* d_out, int out_size)
{
    const float* x  = (const float*)d_in[0];
    const float* wq = (const float*)d_in[1];
    const float* wk = (const float*)d_in[2];
    const float* wv = (const float*)d_in[3];
    float* out = (float*)d_out;

    cudaFuncSetAttribute(proj_mma_kernel,
                         cudaFuncAttributeMaxDynamicSharedMemorySize, PROJ_SMEM);
    cudaFuncSetAttribute(attn_mma_kernel,
                         cudaFuncAttributeMaxDynamicSharedMemorySize, ATT_SMEM);

    dim3 gridP((BSZ * SEQ) / 128, 3);
    proj_mma_kernel<<<gridP, 256, PROJ_SMEM>>>(x, wq, wk, wv);

    dim3 gridA(SEQ / ATT_BQ / 2, BSZ);   // 8 pairs x 16 batches = 128 CTAs
    attn_mma_kernel<<<gridA, 512, ATT_SMEM>>>(out);
}